// round 1
// baseline (speedup 1.0000x reference)
#include <cuda_runtime.h>
#include <math_constants.h>

// Problem constants
#define NN 50000          // nodes
#define NE 800000         // edges
#define FEAT 256          // transformed feature width per node (all 3 layers)
#define INDIM 768
#define BATCH 128
#define ASP 4
#define ODIM 256
#define SLOPE 0.2f

// ---------------- static device scratch (no allocation allowed) ----------------
__device__ float g_fs[(size_t)NN * FEAT];
__device__ float g_fd[(size_t)NN * FEAT];
__device__ float g_h [(size_t)NN * FEAT];
__device__ int   g_deg[NN];
__device__ int   g_off[NN + 1];
__device__ int   g_cur[NN];
__device__ int   g_esrc[NE];
__device__ float g_comb[BATCH * 1024];
__device__ float g_z1[BATCH * 256];
__device__ float g_z2[BATCH * 256];

// ---------------- CSR build ----------------
__global__ void hist_kernel(const int* __restrict__ dst, int* __restrict__ deg) {
    int i = blockIdx.x * blockDim.x + threadIdx.x;
    if (i < NE) atomicAdd(&deg[dst[i]], 1);
}

// Single-block chunked exclusive scan over NN counts -> off[0..NN], cur copy
__global__ void scan_kernel(const int* __restrict__ deg, int* __restrict__ off,
                            int* __restrict__ cur) {
    __shared__ int sm[1024];
    __shared__ int carry;
    int tid = threadIdx.x;
    if (tid == 0) carry = 0;
    __syncthreads();
    for (int base = 0; base < NN; base += 1024) {
        int i = base + tid;
        int v = (i < NN) ? deg[i] : 0;
        sm[tid] = v;
        __syncthreads();
        #pragma unroll
        for (int s = 1; s < 1024; s <<= 1) {
            int t = (tid >= s) ? sm[tid - s] : 0;
            __syncthreads();
            sm[tid] += t;
            __syncthreads();
        }
        int incl = sm[tid];
        int excl = incl - v;
        if (i < NN) {
            off[i] = carry + excl;
            cur[i] = carry + excl;
        }
        __syncthreads();
        if (tid == 1023) carry += incl;
        __syncthreads();
    }
    if (tid == 0) off[NN] = carry;
}

__global__ void scatter_kernel(const int* __restrict__ src, const int* __restrict__ dst,
                               int* __restrict__ cur, int* __restrict__ esrc) {
    int i = blockIdx.x * blockDim.x + threadIdx.x;
    if (i < NE) {
        int pos = atomicAdd(&cur[dst[i]], 1);
        esrc[pos] = src[i];
    }
}

// ---------------- tiled fp32 SGEMM with bias: C[M,N] = A[M,K] @ B[K,N] + bias ----------------
// BM=BN=128, BK=8, 256 threads, 8x8 per-thread tile. N must be multiple of 128, K of 8.
__global__ void __launch_bounds__(256)
sgemm_bias(const float* __restrict__ A, const float* __restrict__ B,
           const float* __restrict__ bias, float* __restrict__ C,
           int M, int N, int K) {
    __shared__ float As[8][128];
    __shared__ float Bs[8][128];
    const int tid = threadIdx.x;
    const int tx = tid & 15;          // 0..15 -> col group
    const int ty = tid >> 4;          // 0..15 -> row group
    const int row0 = blockIdx.y * 128;
    const int col0 = blockIdx.x * 128;

    const int aRow = tid >> 1;         // 0..127
    const int aCol = (tid & 1) * 4;    // 0 or 4
    const int bRow = tid >> 5;         // 0..7
    const int bCol = (tid & 31) * 4;   // 0..124

    float acc[8][8];
    #pragma unroll
    for (int i = 0; i < 8; i++)
        #pragma unroll
        for (int j = 0; j < 8; j++) acc[i][j] = 0.f;

    for (int k0 = 0; k0 < K; k0 += 8) {
        float4 av = make_float4(0.f, 0.f, 0.f, 0.f);
        int gr = row0 + aRow;
        if (gr < M) av = *(const float4*)(A + (size_t)gr * K + k0 + aCol);
        As[aCol + 0][aRow] = av.x;
        As[aCol + 1][aRow] = av.y;
        As[aCol + 2][aRow] = av.z;
        As[aCol + 3][aRow] = av.w;
        float4 bv = *(const float4*)(B + (size_t)(k0 + bRow) * N + col0 + bCol);
        *(float4*)&Bs[bRow][bCol] = bv;
        __syncthreads();
        #pragma unroll
        for (int k = 0; k < 8; k++) {
            float a[8], b[8];
            #pragma unroll
            for (int i = 0; i < 8; i++) a[i] = As[k][ty * 8 + i];
            #pragma unroll
            for (int j = 0; j < 8; j++) b[j] = Bs[k][tx * 8 + j];
            #pragma unroll
            for (int i = 0; i < 8; i++)
                #pragma unroll
                for (int j = 0; j < 8; j++) acc[i][j] += a[i] * b[j];
        }
        __syncthreads();
    }

    #pragma unroll
    for (int i = 0; i < 8; i++) {
        int r = row0 + ty * 8 + i;
        if (r >= M) continue;
        #pragma unroll
        for (int j = 0; j < 8; j += 4) {
            int c = col0 + tx * 8 + j;
            float4 v;
            v.x = acc[i][j + 0] + bias[c + 0];
            v.y = acc[i][j + 1] + bias[c + 1];
            v.z = acc[i][j + 2] + bias[c + 2];
            v.w = acc[i][j + 3] + bias[c + 3];
            *(float4*)(C + (size_t)r * N + c) = v;
        }
    }
}

// ---------------- fused GATv2 edge stage: one warp per dst node, online softmax ----------------
// Per-node layout: 256 floats = heads*fout flat [h*fout + f]. Lane l owns feats [8l, 8l+8).
// G = fout/8 lanes form one head's reduction group (G=8 for fout=64, G=32 for fout=256).
__global__ void __launch_bounds__(256)
edge_agg(const float* __restrict__ fs, const float* __restrict__ fd,
         const float* __restrict__ attn, const int* __restrict__ off,
         const int* __restrict__ esrc, float* __restrict__ out, int G) {
    int warp = (blockIdx.x * blockDim.x + threadIdx.x) >> 5;
    int lane = threadIdx.x & 31;
    if (warp >= NN) return;
    const int v = warp;
    const int s0 = off[v], s1 = off[v + 1];

    const size_t base = (size_t)v * FEAT + lane * 8;
    float4 fd0 = *(const float4*)(fd + base);
    float4 fd1 = *(const float4*)(fd + base + 4);
    float fdv[8] = {fd0.x, fd0.y, fd0.z, fd0.w, fd1.x, fd1.y, fd1.z, fd1.w};
    float4 a0 = *(const float4*)(attn + lane * 8);
    float4 a1 = *(const float4*)(attn + lane * 8 + 4);
    float at[8] = {a0.x, a0.y, a0.z, a0.w, a1.x, a1.y, a1.z, a1.w};

    float m = -CUDART_INF_F;
    float d = 0.f;
    float acc[8];
    #pragma unroll
    for (int j = 0; j < 8; j++) acc[j] = 0.f;

    for (int p = s0; p < s1; p++) {
        int u = esrc[p];
        const size_t ub = (size_t)u * FEAT + lane * 8;
        float4 f0 = *(const float4*)(fs + ub);
        float4 f1 = *(const float4*)(fs + ub + 4);
        float fsu[8] = {f0.x, f0.y, f0.z, f0.w, f1.x, f1.y, f1.z, f1.w};
        float partial = 0.f;
        #pragma unroll
        for (int j = 0; j < 8; j++) {
            float e = fsu[j] + fdv[j];
            float el = (e > 0.f) ? e : SLOPE * e;
            partial += el * at[j];
        }
        // reduce over the G lanes of this head
        #pragma unroll
        for (int sh = 1; sh < 32; sh <<= 1) {
            if (sh < G) partial += __shfl_xor_sync(0xffffffffu, partial, sh);
        }
        float s = partial;
        float nm = fmaxf(m, s);
        float scale = __expf(m - nm);   // exp(-inf)=0 on first edge
        float w = __expf(s - nm);
        d = d * scale + w;
        #pragma unroll
        for (int j = 0; j < 8; j++) acc[j] = acc[j] * scale + w * fsu[j];
        m = nm;
    }

    float inv = (s1 > s0) ? (1.f / d) : 0.f;
    float4 o0, o1;
    o0.x = acc[0] * inv; o0.y = acc[1] * inv; o0.z = acc[2] * inv; o0.w = acc[3] * inv;
    o1.x = acc[4] * inv; o1.y = acc[5] * inv; o1.z = acc[6] * inv; o1.w = acc[7] * inv;
    *(float4*)(out + base) = o0;
    *(float4*)(out + base + 4) = o1;
}

// ---------------- head: build combined [B, 1024] = [aspect_mean(256) | pooled(768)] ----------------
__global__ void build_combined(const float* __restrict__ h, const float* __restrict__ pooled,
                               const int* __restrict__ aidx, float* __restrict__ comb) {
    int i = blockIdx.x * blockDim.x + threadIdx.x;
    if (i >= BATCH * 1024) return;
    int b = i >> 10, j = i & 1023;
    if (j < ODIM) {
        float s = 0.f;
        #pragma unroll
        for (int a = 0; a < ASP; a++) {
            int node = aidx[b * ASP + a];
            s += h[(size_t)node * FEAT + j];
        }
        comb[i] = 0.25f * s;
    } else {
        comb[i] = pooled[(size_t)b * INDIM + (j - ODIM)];
    }
}

// small dense layer: out[B,256] = in[B,K] @ W[K,256] + bias ; optional relu
__global__ void __launch_bounds__(256)
head_mlp(const float* __restrict__ in, const float* __restrict__ W,
         const float* __restrict__ bias, float* __restrict__ out, int K, int relu) {
    __shared__ float row[1024];
    int b = blockIdx.x, j = threadIdx.x;
    for (int k = j; k < K; k += 256) row[k] = in[(size_t)b * K + k];
    __syncthreads();
    float sum = bias[j];
    for (int k = 0; k < K; k++) sum += row[k] * W[(size_t)k * 256 + j];
    if (relu) sum = fmaxf(sum, 0.f);
    out[(size_t)b * 256 + j] = sum;
}

// ---------------- launch ----------------
extern "C" void kernel_launch(void* const* d_in, const int* in_sizes, int n_in,
                              void* d_out, int out_size) {
    // input order (reference signature):
    // 0:x 1:pooled 2:src 3:dst 4:aspect_idx
    // 5:Ws0 6:bs0 7:Wd0 8:bd0 9:attn0
    // 10:Ws1 11:bs1 12:Wd1 13:bd1 14:attn1
    // 15:Ws2 16:bs2 17:Wd2 18:bd2 19:attn2
    // 20:Wc1 21:bc1 22:Wc2 23:bc2 24:Wc3 25:bc3
    const float* x      = (const float*)d_in[0];
    const float* pooled = (const float*)d_in[1];
    const int*   src    = (const int*)d_in[2];
    const int*   dst    = (const int*)d_in[3];
    const int*   aidx   = (const int*)d_in[4];
    const float* Ws[3]  = {(const float*)d_in[5],  (const float*)d_in[10], (const float*)d_in[15]};
    const float* bs[3]  = {(const float*)d_in[6],  (const float*)d_in[11], (const float*)d_in[16]};
    const float* Wd[3]  = {(const float*)d_in[7],  (const float*)d_in[12], (const float*)d_in[17]};
    const float* bd[3]  = {(const float*)d_in[8],  (const float*)d_in[13], (const float*)d_in[18]};
    const float* attn[3]= {(const float*)d_in[9],  (const float*)d_in[14], (const float*)d_in[19]};
    const float* Wc1 = (const float*)d_in[20]; const float* bc1 = (const float*)d_in[21];
    const float* Wc2 = (const float*)d_in[22]; const float* bc2 = (const float*)d_in[23];
    const float* Wc3 = (const float*)d_in[24]; const float* bc3 = (const float*)d_in[25];
    float* out = (float*)d_out;

    float *fs, *fd, *h, *comb, *z1, *z2;
    int *deg, *off, *cur, *esrc;
    cudaGetSymbolAddress((void**)&fs,   g_fs);
    cudaGetSymbolAddress((void**)&fd,   g_fd);
    cudaGetSymbolAddress((void**)&h,    g_h);
    cudaGetSymbolAddress((void**)&deg,  g_deg);
    cudaGetSymbolAddress((void**)&off,  g_off);
    cudaGetSymbolAddress((void**)&cur,  g_cur);
    cudaGetSymbolAddress((void**)&esrc, g_esrc);
    cudaGetSymbolAddress((void**)&comb, g_comb);
    cudaGetSymbolAddress((void**)&z1,   g_z1);
    cudaGetSymbolAddress((void**)&z2,   g_z2);

    // ---- CSR build (same for all 3 layers) ----
    cudaMemsetAsync(deg, 0, NN * sizeof(int));
    hist_kernel<<<(NE + 255) / 256, 256>>>(dst, deg);
    scan_kernel<<<1, 1024>>>(deg, off, cur);
    scatter_kernel<<<(NE + 255) / 256, 256>>>(src, dst, cur, esrc);

    const int gemmBlocks = 256;
    dim3 ggrid(FEAT / 128, (NN + 127) / 128);
    const int aggBlocks = (NN * 32 + 255) / 256;

    // ---- layer 0 (in: x, K=768, heads=4, fout=64 -> G=8) ----
    sgemm_bias<<<ggrid, gemmBlocks>>>(x, Ws[0], bs[0], fs, NN, FEAT, INDIM);
    sgemm_bias<<<ggrid, gemmBlocks>>>(x, Wd[0], bd[0], fd, NN, FEAT, INDIM);
    edge_agg<<<aggBlocks, 256>>>(fs, fd, attn[0], off, esrc, h, 8);

    // ---- layer 1 (in: h, K=256, G=8) ----
    sgemm_bias<<<ggrid, gemmBlocks>>>(h, Ws[1], bs[1], fs, NN, FEAT, FEAT);
    sgemm_bias<<<ggrid, gemmBlocks>>>(h, Wd[1], bd[1], fd, NN, FEAT, FEAT);
    edge_agg<<<aggBlocks, 256>>>(fs, fd, attn[1], off, esrc, h, 8);

    // ---- layer 2 (in: h, K=256, heads=1, fout=256 -> G=32) ----
    sgemm_bias<<<ggrid, gemmBlocks>>>(h, Ws[2], bs[2], fs, NN, FEAT, FEAT);
    sgemm_bias<<<ggrid, gemmBlocks>>>(h, Wd[2], bd[2], fd, NN, FEAT, FEAT);
    edge_agg<<<aggBlocks, 256>>>(fs, fd, attn[2], off, esrc, h, 32);

    // ---- head ----
    build_combined<<<(BATCH * 1024 + 255) / 256, 256>>>(h, pooled, aidx, comb);
    head_mlp<<<BATCH, 256>>>(comb, Wc1, bc1, z1, 1024, 0);
    head_mlp<<<BATCH, 256>>>(z1,   Wc2, bc2, z2, 256, 1);
    head_mlp<<<BATCH, 256>>>(z2,   Wc3, bc3, out, 256, 0);
}

// round 5
// speedup vs baseline: 1.4727x; 1.4727x over previous
#include <cuda_runtime.h>
#include <cuda_bf16.h>
#include <math_constants.h>
#include <cstdint>

// ---------------- problem constants ----------------
#define NN 50000
#define NE 800000
#define FEAT 256
#define INDIM 768
#define BATCH 128
#define ASP 4
#define SLOPE 0.2f

#define MPAD 50048        // 391 * 128
#define FFS 512           // fused fs|fd row stride

// ---------------- static device scratch ----------------
__device__ __nv_bfloat16 g_ahl[(size_t)MPAD * 2 * INDIM];   // A [row][2K]: hi | lo
__device__ __nv_bfloat16 g_baug[(size_t)512 * 3 * INDIM];   // B [n][3K]: hi | hi | lo
__device__ float g_ff[(size_t)MPAD * FFS];                  // fused [fs | fd]
__device__ float g_h [(size_t)NN * FEAT];
__device__ float g_bias[512];
__device__ int   g_deg[NN];
__device__ int   g_off[NN + 1];
__device__ int   g_cur[NN];
__device__ int   g_esrc[NE];
__device__ float g_comb[BATCH * 1024];
__device__ float g_z1[BATCH * 256];
__device__ float g_z2[BATCH * 256];

__device__ __forceinline__ uint32_t smem_u32(const void* p) {
    uint32_t a;
    asm("{ .reg .u64 t; cvta.to.shared.u64 t, %1; cvt.u32.u64 %0, t; }" : "=r"(a) : "l"(p));
    return a;
}

// ---------------- CSR build ----------------
__global__ void hist_kernel(const int* __restrict__ dst, int* __restrict__ deg) {
    int i = blockIdx.x * blockDim.x + threadIdx.x;
    if (i < NE) atomicAdd(&deg[dst[i]], 1);
}
__global__ void scan_kernel(const int* __restrict__ deg, int* __restrict__ off,
                            int* __restrict__ cur) {
    __shared__ int sm[1024];
    __shared__ int carry;
    int tid = threadIdx.x;
    if (tid == 0) carry = 0;
    __syncthreads();
    for (int base = 0; base < NN; base += 1024) {
        int i = base + tid;
        int v = (i < NN) ? deg[i] : 0;
        sm[tid] = v;
        __syncthreads();
        #pragma unroll
        for (int s = 1; s < 1024; s <<= 1) {
            int t = (tid >= s) ? sm[tid - s] : 0;
            __syncthreads();
            sm[tid] += t;
            __syncthreads();
        }
        int incl = sm[tid];
        if (i < NN) { off[i] = carry + incl - v; cur[i] = carry + incl - v; }
        __syncthreads();
        if (tid == 1023) carry += incl;
        __syncthreads();
    }
    if (tid == 0) off[NN] = carry;
}
__global__ void scatter_kernel(const int* __restrict__ src, const int* __restrict__ dst,
                               int* __restrict__ cur, int* __restrict__ esrc) {
    int i = blockIdx.x * blockDim.x + threadIdx.x;
    if (i < NE) {
        int pos = atomicAdd(&cur[dst[i]], 1);
        esrc[pos] = src[i];
    }
}

// ---------------- hi/lo bf16 split conversions ----------------
// A [row][2K]: [0:K]=hi, [K:2K]=lo ; pad rows (>=M) zero
__global__ void conv_a(const float* __restrict__ X, __nv_bfloat16* __restrict__ A,
                       int M, int K) {
    int i = blockIdx.x * blockDim.x + threadIdx.x;
    int q = K >> 2;
    if (i >= MPAD * q) return;
    int row = i / q, c4 = (i - row * q) * 4;
    float4 v = make_float4(0.f, 0.f, 0.f, 0.f);
    if (row < M) v = *(const float4*)(X + (size_t)row * K + c4);
    float vv[4] = {v.x, v.y, v.z, v.w};
    uint16_t hb[4], lb[4];
    #pragma unroll
    for (int j = 0; j < 4; j++) {
        __nv_bfloat16 h = __float2bfloat16_rn(vv[j]);
        float r = vv[j] - __bfloat162float(h);
        __nv_bfloat16 l = __float2bfloat16_rn(r);
        hb[j] = __bfloat16_as_ushort(h);
        lb[j] = __bfloat16_as_ushort(l);
    }
    uint2 hp, lp;
    hp.x = (uint32_t)hb[0] | ((uint32_t)hb[1] << 16);
    hp.y = (uint32_t)hb[2] | ((uint32_t)hb[3] << 16);
    lp.x = (uint32_t)lb[0] | ((uint32_t)lb[1] << 16);
    lp.y = (uint32_t)lb[2] | ((uint32_t)lb[3] << 16);
    __nv_bfloat16* rp = A + (size_t)row * (2 * K);
    *(uint2*)(rp + c4)     = hp;
    *(uint2*)(rp + K + c4) = lp;
}

// B [n][3K]: [0:K]=hi, [K:2K]=hi, [2K:3K]=lo ; n<256 from Ws else Wd (both [K,256])
__global__ void conv_b(const float* __restrict__ Ws, const float* __restrict__ Wd,
                       __nv_bfloat16* __restrict__ B, int K) {
    int i = blockIdx.x * blockDim.x + threadIdx.x;
    if (i >= 512 * K) return;
    int n = i / K, k = i - n * K;
    float w = (n < 256) ? Ws[(size_t)k * 256 + n] : Wd[(size_t)k * 256 + (n - 256)];
    __nv_bfloat16 h = __float2bfloat16_rn(w);
    __nv_bfloat16 l = __float2bfloat16_rn(w - __bfloat162float(h));
    __nv_bfloat16* rp = B + (size_t)n * (3 * K);
    rp[k] = h; rp[K + k] = h; rp[2 * K + k] = l;
}

__global__ void concat_bias(const float* __restrict__ bs, const float* __restrict__ bd,
                            float* __restrict__ bias) {
    int j = threadIdx.x;
    bias[j] = (j < 256) ? bs[j] : bd[j - 256];
}

// ---------------- mma.sync bf16 GEMM ----------------
// C[MPAD,512] = A[hi|lo] x B[hi|hi|lo]^T + bias, 3 K-segments (A reads hi twice).
// CTA tile 128x256, BK=32, 512 threads (16 warps, warp tile 32x64), 3-stage cp.async.
#define BM 128
#define BN 256
#define BK 32
#define ROWB 80                       // 32 bf16 (64B) + 16B pad: conflict-free ldmatrix
#define ASM_BYTES (BM * ROWB)         // 10240
#define BSM_BYTES (BN * ROWB)         // 20480
#define BUF_BYTES (ASM_BYTES + BSM_BYTES)
#define NSTAGE 3
#define SMEM_GEMM (NSTAGE * BUF_BYTES)   // 92160

__global__ void __launch_bounds__(512, 1)
gemm_mma(const __nv_bfloat16* __restrict__ A, const __nv_bfloat16* __restrict__ B,
         const float* __restrict__ bias, float* __restrict__ C, int K) {
    extern __shared__ char smem[];
    const uint32_t sb = smem_u32(smem);
    const int tid = threadIdx.x;
    const int wid = tid >> 5, lane = tid & 31;
    const int wm = (wid & 3) * 32;
    const int wn = (wid >> 2) * 64;
    const int m0 = blockIdx.y * BM;
    const int n0 = blockIdx.x * BN;
    const int ldA = 2 * K;
    const int ldB = 3 * K;
    const int kseg = K / BK;
    const int NC = 3 * kseg;

    float acc[2][8][4];
    #pragma unroll
    for (int i = 0; i < 2; i++)
        #pragma unroll
        for (int j = 0; j < 8; j++)
            #pragma unroll
            for (int q = 0; q < 4; q++) acc[i][j][q] = 0.f;

    // per-thread load coords
    const int ar = tid >> 2, ac = tid & 3;            // A: 1 x 16B chunk
    const int br0 = tid >> 1, bc0 = (tid & 1) * 2;    // B: 2 x 16B chunks (cols 0,1 or 2,3)

    #define ISSUE(kc, buf) do {                                                        \
        int _seg = (kc) / kseg, _wk = (kc) - _seg * kseg;                              \
        int _acol = ((_seg == 1) ? K : 0) + _wk * BK;                                  \
        int _bcol = (kc) * BK;                                                         \
        uint32_t _ab = sb + (buf) * BUF_BYTES;                                         \
        uint32_t _bb = _ab + ASM_BYTES;                                                \
        {                                                                              \
            uint32_t s = _ab + ar * ROWB + ac * 16;                                    \
            const char* g = (const char*)(A + (size_t)(m0 + ar) * ldA + _acol) + ac * 16; \
            asm volatile("cp.async.cg.shared.global [%0], [%1], 16;" :: "r"(s), "l"(g)); \
        }                                                                              \
        _Pragma("unroll")                                                              \
        for (int _i = 0; _i < 2; _i++) {                                               \
            int _c = bc0 + _i;                                                         \
            uint32_t s = _bb + br0 * ROWB + _c * 16;                                   \
            const char* g = (const char*)(B + (size_t)(n0 + br0) * ldB + _bcol) + _c * 16; \
            asm volatile("cp.async.cg.shared.global [%0], [%1], 16;" :: "r"(s), "l"(g)); \
        }                                                                              \
        asm volatile("cp.async.commit_group;");                                        \
    } while (0)

    ISSUE(0, 0);
    if (NC > 1) ISSUE(1, 1);

    for (int kc = 0; kc < NC; kc++) {
        int buf = kc % NSTAGE;
        if (kc + 2 < NC) {
            ISSUE(kc + 2, (kc + 2) % NSTAGE);
            asm volatile("cp.async.wait_group 2;");
        } else if (kc + 1 < NC) {
            asm volatile("cp.async.wait_group 1;");
        } else {
            asm volatile("cp.async.wait_group 0;");
        }
        __syncthreads();

        uint32_t ab = sb + buf * BUF_BYTES;
        uint32_t bb = ab + ASM_BYTES;
        #pragma unroll
        for (int ks = 0; ks < 2; ks++) {
            uint32_t a[2][4], b[4][4];
            #pragma unroll
            for (int mi = 0; mi < 2; mi++) {
                uint32_t addr = ab + (uint32_t)(wm + mi * 16 + (lane & 15)) * ROWB
                              + (uint32_t)(ks * 32 + (lane >> 4) * 16);
                asm volatile("ldmatrix.sync.aligned.m8n8.x4.shared.b16 {%0,%1,%2,%3}, [%4];"
                    : "=r"(a[mi][0]), "=r"(a[mi][1]), "=r"(a[mi][2]), "=r"(a[mi][3])
                    : "r"(addr));
            }
            #pragma unroll
            for (int nb = 0; nb < 4; nb++) {
                int n = wn + nb * 16 + ((lane >> 4) << 3) + (lane & 7);
                int k = ks * 16 + (((lane >> 3) & 1) << 3);
                uint32_t addr = bb + (uint32_t)n * ROWB + (uint32_t)k * 2;
                asm volatile("ldmatrix.sync.aligned.m8n8.x4.shared.b16 {%0,%1,%2,%3}, [%4];"
                    : "=r"(b[nb][0]), "=r"(b[nb][1]), "=r"(b[nb][2]), "=r"(b[nb][3])
                    : "r"(addr));
            }
            #pragma unroll
            for (int mi = 0; mi < 2; mi++)
                #pragma unroll
                for (int ni = 0; ni < 8; ni++) {
                    asm volatile(
                        "mma.sync.aligned.m16n8k16.row.col.f32.bf16.bf16.f32 "
                        "{%0,%1,%2,%3}, {%4,%5,%6,%7}, {%8,%9}, {%0,%1,%2,%3};"
                        : "+f"(acc[mi][ni][0]), "+f"(acc[mi][ni][1]),
                          "+f"(acc[mi][ni][2]), "+f"(acc[mi][ni][3])
                        : "r"(a[mi][0]), "r"(a[mi][1]), "r"(a[mi][2]), "r"(a[mi][3]),
                          "r"(b[ni >> 1][(ni & 1) * 2]), "r"(b[ni >> 1][(ni & 1) * 2 + 1]));
                }
        }
        __syncthreads();
    }
    #undef ISSUE

    // epilogue
    #pragma unroll
    for (int mi = 0; mi < 2; mi++) {
        int r0 = m0 + wm + mi * 16 + (lane >> 2);
        #pragma unroll
        for (int ni = 0; ni < 8; ni++) {
            int col = n0 + wn + ni * 8 + (lane & 3) * 2;
            float bx = bias[col], by = bias[col + 1];
            float2 v0 = make_float2(acc[mi][ni][0] + bx, acc[mi][ni][1] + by);
            float2 v1 = make_float2(acc[mi][ni][2] + bx, acc[mi][ni][3] + by);
            *(float2*)(C + (size_t)r0 * FFS + col) = v0;
            *(float2*)(C + (size_t)(r0 + 8) * FFS + col) = v1;
        }
    }
}

// ---------------- fused GATv2 edge stage (ff rows: fs at +0, fd at +256) ----------------
__global__ void __launch_bounds__(256)
edge_agg(const float* __restrict__ ff, const float* __restrict__ attn,
         const int* __restrict__ off, const int* __restrict__ esrc,
         float* __restrict__ out, int G) {
    int warp = (blockIdx.x * blockDim.x + threadIdx.x) >> 5;
    int lane = threadIdx.x & 31;
    if (warp >= NN) return;
    const int v = warp;
    const int s0 = off[v], s1 = off[v + 1];

    const float* fdp = ff + (size_t)v * FFS + 256 + lane * 8;
    float4 fd0 = *(const float4*)(fdp);
    float4 fd1 = *(const float4*)(fdp + 4);
    float fdv[8] = {fd0.x, fd0.y, fd0.z, fd0.w, fd1.x, fd1.y, fd1.z, fd1.w};
    float4 a0 = *(const float4*)(attn + lane * 8);
    float4 a1 = *(const float4*)(attn + lane * 8 + 4);
    float at[8] = {a0.x, a0.y, a0.z, a0.w, a1.x, a1.y, a1.z, a1.w};

    float m = -CUDART_INF_F, d = 0.f;
    float acc[8];
    #pragma unroll
    for (int j = 0; j < 8; j++) acc[j] = 0.f;

    for (int p = s0; p < s1; p++) {
        int u = esrc[p];
        const float* fsp = ff + (size_t)u * FFS + lane * 8;
        float4 f0 = *(const float4*)(fsp);
        float4 f1 = *(const float4*)(fsp + 4);
        float fsu[8] = {f0.x, f0.y, f0.z, f0.w, f1.x, f1.y, f1.z, f1.w};
        float partial = 0.f;
        #pragma unroll
        for (int j = 0; j < 8; j++) {
            float e = fsu[j] + fdv[j];
            float el = (e > 0.f) ? e : SLOPE * e;
            partial += el * at[j];
        }
        #pragma unroll
        for (int sh = 1; sh < 32; sh <<= 1)
            if (sh < G) partial += __shfl_xor_sync(0xffffffffu, partial, sh);
        float s = partial;
        float nm = fmaxf(m, s);
        float scale = __expf(m - nm);
        float w = __expf(s - nm);
        d = d * scale + w;
        #pragma unroll
        for (int j = 0; j < 8; j++) acc[j] = acc[j] * scale + w * fsu[j];
        m = nm;
    }

    float inv = (s1 > s0) ? (1.f / d) : 0.f;
    float* op = out + (size_t)v * FEAT + lane * 8;
    float4 o0, o1;
    o0.x = acc[0] * inv; o0.y = acc[1] * inv; o0.z = acc[2] * inv; o0.w = acc[3] * inv;
    o1.x = acc[4] * inv; o1.y = acc[5] * inv; o1.z = acc[6] * inv; o1.w = acc[7] * inv;
    *(float4*)(op) = o0;
    *(float4*)(op + 4) = o1;
}

// ---------------- head ----------------
__global__ void build_combined(const float* __restrict__ h, const float* __restrict__ pooled,
                               const int* __restrict__ aidx, float* __restrict__ comb) {
    int i = blockIdx.x * blockDim.x + threadIdx.x;
    if (i >= BATCH * 1024) return;
    int b = i >> 10, j = i & 1023;
    if (j < 256) {
        float s = 0.f;
        #pragma unroll
        for (int a = 0; a < ASP; a++) {
            int node = aidx[b * ASP + a];
            s += h[(size_t)node * FEAT + j];
        }
        comb[i] = 0.25f * s;
    } else {
        comb[i] = pooled[(size_t)b * INDIM + (j - 256)];
    }
}

__global__ void __launch_bounds__(256)
head_mlp(const float* __restrict__ in, const float* __restrict__ W,
         const float* __restrict__ bias, float* __restrict__ out, int K, int relu) {
    __shared__ float row[1024];
    int b = blockIdx.x, j = threadIdx.x;
    for (int k = j; k < K; k += 256) row[k] = in[(size_t)b * K + k];
    __syncthreads();
    float sum = bias[j];
    for (int k = 0; k < K; k++) sum += row[k] * W[(size_t)k * 256 + j];
    if (relu) sum = fmaxf(sum, 0.f);
    out[(size_t)b * 256 + j] = sum;
}

// ---------------- launch ----------------
extern "C" void kernel_launch(void* const* d_in, const int* in_sizes, int n_in,
                              void* d_out, int out_size) {
    const float* x      = (const float*)d_in[0];
    const float* pooled = (const float*)d_in[1];
    const int*   src    = (const int*)d_in[2];
    const int*   dst    = (const int*)d_in[3];
    const int*   aidx   = (const int*)d_in[4];
    const float* Ws[3]  = {(const float*)d_in[5],  (const float*)d_in[10], (const float*)d_in[15]};
    const float* bs[3]  = {(const float*)d_in[6],  (const float*)d_in[11], (const float*)d_in[16]};
    const float* Wd[3]  = {(const float*)d_in[7],  (const float*)d_in[12], (const float*)d_in[17]};
    const float* bd[3]  = {(const float*)d_in[8],  (const float*)d_in[13], (const float*)d_in[18]};
    const float* attn[3]= {(const float*)d_in[9],  (const float*)d_in[14], (const float*)d_in[19]};
    const float* Wc1 = (const float*)d_in[20]; const float* bc1 = (const float*)d_in[21];
    const float* Wc2 = (const float*)d_in[22]; const float* bc2 = (const float*)d_in[23];
    const float* Wc3 = (const float*)d_in[24]; const float* bc3 = (const float*)d_in[25];
    float* out = (float*)d_out;

    __nv_bfloat16 *ahl, *baug;
    float *ff, *h, *bias, *comb, *z1, *z2;
    int *deg, *off, *cur, *esrc;
    cudaGetSymbolAddress((void**)&ahl,  g_ahl);
    cudaGetSymbolAddress((void**)&baug, g_baug);
    cudaGetSymbolAddress((void**)&ff,   g_ff);
    cudaGetSymbolAddress((void**)&h,    g_h);
    cudaGetSymbolAddress((void**)&bias, g_bias);
    cudaGetSymbolAddress((void**)&deg,  g_deg);
    cudaGetSymbolAddress((void**)&off,  g_off);
    cudaGetSymbolAddress((void**)&cur,  g_cur);
    cudaGetSymbolAddress((void**)&esrc, g_esrc);
    cudaGetSymbolAddress((void**)&comb, g_comb);
    cudaGetSymbolAddress((void**)&z1,   g_z1);
    cudaGetSymbolAddress((void**)&z2,   g_z2);

    cudaFuncSetAttribute(gemm_mma, cudaFuncAttributeMaxDynamicSharedMemorySize, SMEM_GEMM);

    // ---- CSR build ----
    cudaMemsetAsync(deg, 0, NN * sizeof(int));
    hist_kernel<<<(NE + 255) / 256, 256>>>(dst, deg);
    scan_kernel<<<1, 1024>>>(deg, off, cur);
    scatter_kernel<<<(NE + 255) / 256, 256>>>(src, dst, cur, esrc);

    dim3 ggrid(512 / BN, MPAD / BM);   // (2, 391)
    const int aggBlocks = (NN * 32 + 255) / 256;

    // ---- layer 0: input x [NN, 768] ----
    {
        int K = INDIM;
        conv_a<<<(MPAD * (K / 4) + 255) / 256, 256>>>(x, ahl, NN, K);
        conv_b<<<(512 * K + 255) / 256, 256>>>(Ws[0], Wd[0], baug, K);
        concat_bias<<<1, 512>>>(bs[0], bd[0], bias);
        gemm_mma<<<ggrid, 512, SMEM_GEMM>>>(ahl, baug, bias, ff, K);
        edge_agg<<<aggBlocks, 256>>>(ff, attn[0], off, esrc, h, 8);
    }
    // ---- layer 1: input h [NN, 256] ----
    {
        int K = FEAT;
        conv_a<<<(MPAD * (K / 4) + 255) / 256, 256>>>(h, ahl, NN, K);
        conv_b<<<(512 * K + 255) / 256, 256>>>(Ws[1], Wd[1], baug, K);
        concat_bias<<<1, 512>>>(bs[1], bd[1], bias);
        gemm_mma<<<ggrid, 512, SMEM_GEMM>>>(ahl, baug, bias, ff, K);
        edge_agg<<<aggBlocks, 256>>>(ff, attn[1], off, esrc, h, 8);
    }
    // ---- layer 2: input h [NN, 256], heads=1 fout=256 -> G=32 ----
    {
        int K = FEAT;
        conv_a<<<(MPAD * (K / 4) + 255) / 256, 256>>>(h, ahl, NN, K);
        conv_b<<<(512 * K + 255) / 256, 256>>>(Ws[2], Wd[2], baug, K);
        concat_bias<<<1, 512>>>(bs[2], bd[2], bias);
        gemm_mma<<<ggrid, 512, SMEM_GEMM>>>(ahl, baug, bias, ff, K);
        edge_agg<<<aggBlocks, 256>>>(ff, attn[2], off, esrc, h, 32);
    }

    // ---- head ----
    build_combined<<<(BATCH * 1024 + 255) / 256, 256>>>(h, pooled, aidx, comb);
    head_mlp<<<BATCH, 256>>>(comb, Wc1, bc1, z1, 1024, 0);
    head_mlp<<<BATCH, 256>>>(z1,   Wc2, bc2, z2, 256, 1);
    head_mlp<<<BATCH, 256>>>(z2,   Wc3, bc3, out, 256, 0);
}

// round 13
// speedup vs baseline: 2.6093x; 1.7717x over previous
#include <cuda_runtime.h>
#include <cuda_fp16.h>
#include <math_constants.h>
#include <cstdint>

// ---------------- problem constants ----------------
#define NN 50000
#define NE 800000
#define FEAT 256
#define INDIM 768
#define BATCH 128
#define ASP 4
#define SLOPE 0.2f

#define MPAD 50048        // 391 * 128
#define FFS 512           // fused fs|fd row stride

// ---------------- static device scratch ----------------
__device__ __half g_a [(size_t)MPAD * INDIM];    // GEMM A (fp16): layer0 K=768, layers1/2 K=256
__device__ __half g_b [(size_t)512 * INDIM];     // GEMM B^T (fp16) [512, K]
__device__ __half g_ff[(size_t)MPAD * FFS];      // fused [fs | fd] fp16
__device__ float  g_h [(size_t)NN * FEAT];       // layer-2 output (fp32 for head)
__device__ float  g_bias[512];
__device__ int    g_deg[NN];
__device__ int    g_off[NN + 1];
__device__ int    g_cur[NN];
__device__ int    g_esrc[NE];
__device__ float  g_comb[BATCH * 1024];
__device__ float  g_z1[BATCH * 256];
__device__ float  g_z2[BATCH * 256];

__device__ __forceinline__ uint32_t smem_u32(const void* p) {
    uint32_t a;
    asm("{ .reg .u64 t; cvta.to.shared.u64 t, %1; cvt.u32.u64 %0, t; }" : "=r"(a) : "l"(p));
    return a;
}

// ---------------- CSR build ----------------
__global__ void hist_kernel(const int* __restrict__ dst, int* __restrict__ deg) {
    int i = blockIdx.x * blockDim.x + threadIdx.x;
    if (i < NE) atomicAdd(&deg[dst[i]], 1);
}

// 1024-thread shuffle-based chunked exclusive scan
__global__ void scan_kernel(const int* __restrict__ deg, int* __restrict__ off,
                            int* __restrict__ cur) {
    __shared__ int wsum[32];
    __shared__ int carry;
    const int tid = threadIdx.x;
    const int lane = tid & 31, wid = tid >> 5;
    if (tid == 0) carry = 0;
    __syncthreads();
    for (int base = 0; base < NN; base += 1024) {
        int i = base + tid;
        int v = (i < NN) ? deg[i] : 0;
        int x = v;
        #pragma unroll
        for (int s = 1; s < 32; s <<= 1) {
            int t = __shfl_up_sync(0xffffffffu, x, s);
            if (lane >= s) x += t;
        }
        if (lane == 31) wsum[wid] = x;
        __syncthreads();
        if (wid == 0) {
            int y = wsum[lane];
            #pragma unroll
            for (int s = 1; s < 32; s <<= 1) {
                int t = __shfl_up_sync(0xffffffffu, y, s);
                if (lane >= s) y += t;
            }
            wsum[lane] = y;
        }
        __syncthreads();
        int incl = x + (wid ? wsum[wid - 1] : 0);
        int excl = carry + incl - v;
        if (i < NN) { off[i] = excl; cur[i] = excl; }
        __syncthreads();
        if (tid == 0) carry += wsum[31];
        __syncthreads();
    }
    if (tid == 0) off[NN] = carry;
}

__global__ void scatter_kernel(const int* __restrict__ src, const int* __restrict__ dst,
                               int* __restrict__ cur, int* __restrict__ esrc) {
    int i = blockIdx.x * blockDim.x + threadIdx.x;
    if (i < NE) {
        int pos = atomicAdd(&cur[dst[i]], 1);
        esrc[pos] = src[i];
    }
}

// ---------------- fp16 conversions ----------------
// A = fp16(X) [MPAD x K], pad rows zero (layer 0 only)
__global__ void conv_a_f16(const float* __restrict__ X, __half* __restrict__ A,
                           int M, int K) {
    int i = blockIdx.x * blockDim.x + threadIdx.x;
    int q = K >> 2;
    if (i >= MPAD * q) return;
    int row = i / q, c4 = (i - row * q) * 4;
    float4 v = make_float4(0.f, 0.f, 0.f, 0.f);
    if (row < M) v = *(const float4*)(X + (size_t)row * K + c4);
    __half2 h0 = __floats2half2_rn(v.x, v.y);
    __half2 h1 = __floats2half2_rn(v.z, v.w);
    uint2 pk;
    pk.x = *(uint32_t*)&h0;
    pk.y = *(uint32_t*)&h1;
    *(uint2*)(A + (size_t)row * K + c4) = pk;
}

// B[n][k] = fp16(W(k, n)) ; n<256 from Ws else Wd (both [K,256])
__global__ void conv_b_f16(const float* __restrict__ Ws, const float* __restrict__ Wd,
                           __half* __restrict__ B, int K) {
    int i = blockIdx.x * blockDim.x + threadIdx.x;
    if (i >= 512 * K) return;
    int n = i / K, k = i - n * K;
    float w = (n < 256) ? Ws[(size_t)k * 256 + n] : Wd[(size_t)k * 256 + (n - 256)];
    B[(size_t)n * K + k] = __float2half_rn(w);
}

__global__ void concat_bias(const float* __restrict__ bs, const float* __restrict__ bd,
                            float* __restrict__ bias) {
    int j = threadIdx.x;
    bias[j] = (j < 256) ? bs[j] : bd[j - 256];
}

// ---------------- mma.sync fp16 GEMM: C[MPAD,512](fp16) = A[MPAD,K] @ B[512,K]^T + bias ----------------
// CTA tile 128x256, BK=32, 512 threads (16 warps, warp tile 32x64), 3-stage cp.async.
#define BM 128
#define BN 256
#define BK 32
#define ROWB 80
#define ASM_BYTES (BM * ROWB)
#define BSM_BYTES (BN * ROWB)
#define BUF_BYTES (ASM_BYTES + BSM_BYTES)
#define NSTAGE 3
#define SMEM_GEMM (NSTAGE * BUF_BYTES)   // 92160

__global__ void __launch_bounds__(512, 1)
gemm_mma(const __half* __restrict__ A, const __half* __restrict__ B,
         const float* __restrict__ bias, __half* __restrict__ C, int K) {
    extern __shared__ char smem[];
    const uint32_t sb = smem_u32(smem);
    const int tid = threadIdx.x;
    const int wid = tid >> 5, lane = tid & 31;
    const int wm = (wid & 3) * 32;
    const int wn = (wid >> 2) * 64;
    const int m0 = blockIdx.y * BM;
    const int n0 = blockIdx.x * BN;
    const int NC = K / BK;

    float acc[2][8][4];
    #pragma unroll
    for (int i = 0; i < 2; i++)
        #pragma unroll
        for (int j = 0; j < 8; j++)
            #pragma unroll
            for (int q = 0; q < 4; q++) acc[i][j][q] = 0.f;

    const int ar = tid >> 2, ac = tid & 3;
    const int br0 = tid >> 1, bc0 = (tid & 1) * 2;

    #define ISSUE(kc, buf) do {                                                        \
        int _col = (kc) * BK;                                                          \
        uint32_t _ab = sb + (buf) * BUF_BYTES;                                         \
        uint32_t _bb = _ab + ASM_BYTES;                                                \
        {                                                                              \
            uint32_t s = _ab + ar * ROWB + ac * 16;                                    \
            const char* g = (const char*)(A + (size_t)(m0 + ar) * K + _col) + ac * 16; \
            asm volatile("cp.async.cg.shared.global [%0], [%1], 16;" :: "r"(s), "l"(g)); \
        }                                                                              \
        _Pragma("unroll")                                                              \
        for (int _i = 0; _i < 2; _i++) {                                               \
            int _c = bc0 + _i;                                                         \
            uint32_t s = _bb + br0 * ROWB + _c * 16;                                   \
            const char* g = (const char*)(B + (size_t)(n0 + br0) * K + _col) + _c * 16; \
            asm volatile("cp.async.cg.shared.global [%0], [%1], 16;" :: "r"(s), "l"(g)); \
        }                                                                              \
        asm volatile("cp.async.commit_group;");                                        \
    } while (0)

    ISSUE(0, 0);
    if (NC > 1) ISSUE(1, 1);

    for (int kc = 0; kc < NC; kc++) {
        int buf = kc % NSTAGE;
        if (kc + 2 < NC) {
            ISSUE(kc + 2, (kc + 2) % NSTAGE);
            asm volatile("cp.async.wait_group 2;");
        } else if (kc + 1 < NC) {
            asm volatile("cp.async.wait_group 1;");
        } else {
            asm volatile("cp.async.wait_group 0;");
        }
        __syncthreads();

        uint32_t ab = sb + buf * BUF_BYTES;
        uint32_t bb = ab + ASM_BYTES;
        #pragma unroll
        for (int ks = 0; ks < 2; ks++) {
            uint32_t a[2][4], b[4][4];
            #pragma unroll
            for (int mi = 0; mi < 2; mi++) {
                uint32_t addr = ab + (uint32_t)(wm + mi * 16 + (lane & 15)) * ROWB
                              + (uint32_t)(ks * 32 + (lane >> 4) * 16);
                asm volatile("ldmatrix.sync.aligned.m8n8.x4.shared.b16 {%0,%1,%2,%3}, [%4];"
                    : "=r"(a[mi][0]), "=r"(a[mi][1]), "=r"(a[mi][2]), "=r"(a[mi][3])
                    : "r"(addr));
            }
            #pragma unroll
            for (int nb = 0; nb < 4; nb++) {
                int n = wn + nb * 16 + ((lane >> 4) << 3) + (lane & 7);
                int k = ks * 16 + (((lane >> 3) & 1) << 3);
                uint32_t addr = bb + (uint32_t)n * ROWB + (uint32_t)k * 2;
                asm volatile("ldmatrix.sync.aligned.m8n8.x4.shared.b16 {%0,%1,%2,%3}, [%4];"
                    : "=r"(b[nb][0]), "=r"(b[nb][1]), "=r"(b[nb][2]), "=r"(b[nb][3])
                    : "r"(addr));
            }
            #pragma unroll
            for (int mi = 0; mi < 2; mi++)
                #pragma unroll
                for (int ni = 0; ni < 8; ni++) {
                    asm volatile(
                        "mma.sync.aligned.m16n8k16.row.col.f32.f16.f16.f32 "
                        "{%0,%1,%2,%3}, {%4,%5,%6,%7}, {%8,%9}, {%0,%1,%2,%3};"
                        : "+f"(acc[mi][ni][0]), "+f"(acc[mi][ni][1]),
                          "+f"(acc[mi][ni][2]), "+f"(acc[mi][ni][3])
                        : "r"(a[mi][0]), "r"(a[mi][1]), "r"(a[mi][2]), "r"(a[mi][3]),
                          "r"(b[ni >> 1][(ni & 1) * 2]), "r"(b[ni >> 1][(ni & 1) * 2 + 1]));
                }
        }
        __syncthreads();
    }
    #undef ISSUE

    // epilogue: fp16 out
    #pragma unroll
    for (int mi = 0; mi < 2; mi++) {
        int r0 = m0 + wm + mi * 16 + (lane >> 2);
        #pragma unroll
        for (int ni = 0; ni < 8; ni++) {
            int col = n0 + wn + ni * 8 + (lane & 3) * 2;
            float bx = bias[col], by = bias[col + 1];
            __half2 v0 = __floats2half2_rn(acc[mi][ni][0] + bx, acc[mi][ni][1] + by);
            __half2 v1 = __floats2half2_rn(acc[mi][ni][2] + bx, acc[mi][ni][3] + by);
            *(__half2*)(C + (size_t)r0 * FFS + col) = v0;
            *(__half2*)(C + (size_t)(r0 + 8) * FFS + col) = v1;
        }
    }
}

// ---------------- fused GATv2 edge stage (fp16 ff rows: fs at +0, fd at +256) ----------------
__device__ __forceinline__ void load8h(const __half* p, float* out) {
    uint4 w = *(const uint4*)p;
    const __half2* hp = (const __half2*)&w;
    float2 f0 = __half22float2(hp[0]);
    float2 f1 = __half22float2(hp[1]);
    float2 f2 = __half22float2(hp[2]);
    float2 f3 = __half22float2(hp[3]);
    out[0] = f0.x; out[1] = f0.y; out[2] = f1.x; out[3] = f1.y;
    out[4] = f2.x; out[5] = f2.y; out[6] = f3.x; out[7] = f3.y;
}

template <bool OUT_HALF>
__global__ void __launch_bounds__(256)
edge_agg(const __half* __restrict__ ff, const float* __restrict__ attn,
         const int* __restrict__ off, const int* __restrict__ esrc,
         __half* __restrict__ outh, float* __restrict__ outf, int G) {
    int warp = (blockIdx.x * blockDim.x + threadIdx.x) >> 5;
    int lane = threadIdx.x & 31;
    if (warp >= NN) return;
    const int v = warp;
    const int s0 = off[v], s1 = off[v + 1];

    float fdv[8];
    load8h(ff + (size_t)v * FFS + 256 + lane * 8, fdv);
    float4 a0 = *(const float4*)(attn + lane * 8);
    float4 a1 = *(const float4*)(attn + lane * 8 + 4);
    float at[8] = {a0.x, a0.y, a0.z, a0.w, a1.x, a1.y, a1.z, a1.w};

    float m = -CUDART_INF_F, d = 0.f;
    float acc[8];
    #pragma unroll
    for (int j = 0; j < 8; j++) acc[j] = 0.f;

    for (int p = s0; p < s1; p++) {
        int u = esrc[p];
        float fsu[8];
        load8h(ff + (size_t)u * FFS + lane * 8, fsu);
        float partial = 0.f;
        #pragma unroll
        for (int j = 0; j < 8; j++) {
            float e = fsu[j] + fdv[j];
            float el = (e > 0.f) ? e : SLOPE * e;
            partial += el * at[j];
        }
        #pragma unroll
        for (int sh = 1; sh < 32; sh <<= 1)
            if (sh < G) partial += __shfl_xor_sync(0xffffffffu, partial, sh);
        float s = partial;
        float nm = fmaxf(m, s);
        float scale = __expf(m - nm);
        float w = __expf(s - nm);
        d = d * scale + w;
        #pragma unroll
        for (int j = 0; j < 8; j++) acc[j] = acc[j] * scale + w * fsu[j];
        m = nm;
    }

    float inv = (s1 > s0) ? (1.f / d) : 0.f;
    if (OUT_HALF) {
        __half2 h[4];
        #pragma unroll
        for (int j = 0; j < 4; j++)
            h[j] = __floats2half2_rn(acc[2 * j] * inv, acc[2 * j + 1] * inv);
        *(uint4*)(outh + (size_t)v * FEAT + lane * 8) = *(uint4*)h;
    } else {
        float* op = outf + (size_t)v * FEAT + lane * 8;
        float4 o0, o1;
        o0.x = acc[0] * inv; o0.y = acc[1] * inv; o0.z = acc[2] * inv; o0.w = acc[3] * inv;
        o1.x = acc[4] * inv; o1.y = acc[5] * inv; o1.z = acc[6] * inv; o1.w = acc[7] * inv;
        *(float4*)(op) = o0;
        *(float4*)(op + 4) = o1;
    }
}

// ---------------- head ----------------
__global__ void build_combined(const float* __restrict__ h, const float* __restrict__ pooled,
                               const int* __restrict__ aidx, float* __restrict__ comb) {
    int i = blockIdx.x * blockDim.x + threadIdx.x;
    if (i >= BATCH * 1024) return;
    int b = i >> 10, j = i & 1023;
    if (j < 256) {
        float s = 0.f;
        #pragma unroll
        for (int a = 0; a < ASP; a++) {
            int node = aidx[b * ASP + a];
            s += h[(size_t)node * FEAT + j];
        }
        comb[i] = 0.25f * s;
    } else {
        comb[i] = pooled[(size_t)b * INDIM + (j - 256)];
    }
}

__global__ void __launch_bounds__(256)
head_mlp(const float* __restrict__ in, const float* __restrict__ W,
         const float* __restrict__ bias, float* __restrict__ out, int K, int relu) {
    __shared__ float row[1024];
    int b = blockIdx.x, j = threadIdx.x;
    for (int k = j; k < K; k += 256) row[k] = in[(size_t)b * K + k];
    __syncthreads();
    float sum = bias[j];
    for (int k = 0; k < K; k++) sum += row[k] * W[(size_t)k * 256 + j];
    if (relu) sum = fmaxf(sum, 0.f);
    out[(size_t)b * 256 + j] = sum;
}

// ---------------- launch ----------------
extern "C" void kernel_launch(void* const* d_in, const int* in_sizes, int n_in,
                              void* d_out, int out_size) {
    const float* x      = (const float*)d_in[0];
    const float* pooled = (const float*)d_in[1];
    const int*   src    = (const int*)d_in[2];
    const int*   dst    = (const int*)d_in[3];
    const int*   aidx   = (const int*)d_in[4];
    const float* Ws[3]  = {(const float*)d_in[5],  (const float*)d_in[10], (const float*)d_in[15]};
    const float* bs[3]  = {(const float*)d_in[6],  (const float*)d_in[11], (const float*)d_in[16]};
    const float* Wd[3]  = {(const float*)d_in[7],  (const float*)d_in[12], (const float*)d_in[17]};
    const float* bd[3]  = {(const float*)d_in[8],  (const float*)d_in[13], (const float*)d_in[18]};
    const float* attn[3]= {(const float*)d_in[9],  (const float*)d_in[14], (const float*)d_in[19]};
    const float* Wc1 = (const float*)d_in[20]; const float* bc1 = (const float*)d_in[21];
    const float* Wc2 = (const float*)d_in[22]; const float* bc2 = (const float*)d_in[23];
    const float* Wc3 = (const float*)d_in[24]; const float* bc3 = (const float*)d_in[25];
    float* out = (float*)d_out;

    __half *A, *B, *ff;
    float *h, *bias, *comb, *z1, *z2;
    int *deg, *off, *cur, *esrc;
    cudaGetSymbolAddress((void**)&A,    g_a);
    cudaGetSymbolAddress((void**)&B,    g_b);
    cudaGetSymbolAddress((void**)&ff,   g_ff);
    cudaGetSymbolAddress((void**)&h,    g_h);
    cudaGetSymbolAddress((void**)&bias, g_bias);
    cudaGetSymbolAddress((void**)&deg,  g_deg);
    cudaGetSymbolAddress((void**)&off,  g_off);
    cudaGetSymbolAddress((void**)&cur,  g_cur);
    cudaGetSymbolAddress((void**)&esrc, g_esrc);
    cudaGetSymbolAddress((void**)&comb, g_comb);
    cudaGetSymbolAddress((void**)&z1,   g_z1);
    cudaGetSymbolAddress((void**)&z2,   g_z2);

    cudaFuncSetAttribute(gemm_mma, cudaFuncAttributeMaxDynamicSharedMemorySize, SMEM_GEMM);

    // ---- CSR build ----
    cudaMemsetAsync(deg, 0, NN * sizeof(int));
    hist_kernel<<<(NE + 255) / 256, 256>>>(dst, deg);
    scan_kernel<<<1, 1024>>>(deg, off, cur);
    scatter_kernel<<<(NE + 255) / 256, 256>>>(src, dst, cur, esrc);

    dim3 ggrid(512 / BN, MPAD / BM);   // (2, 391)
    const int aggBlocks = (NN * 32 + 255) / 256;

    // ---- layer 0: input x [NN, 768] ----
    {
        int K = INDIM;
        conv_a_f16<<<(MPAD * (K / 4) + 255) / 256, 256>>>(x, A, NN, K);
        conv_b_f16<<<(512 * K + 255) / 256, 256>>>(Ws[0], Wd[0], B, K);
        concat_bias<<<1, 512>>>(bs[0], bd[0], bias);
        gemm_mma<<<ggrid, 512, SMEM_GEMM>>>(A, B, bias, ff, K);
        edge_agg<true><<<aggBlocks, 256>>>(ff, attn[0], off, esrc, A, nullptr, 8);
        // zero pad rows of A (K=256 layout: rows NN..MPAD are contiguous tail)
        cudaMemsetAsync(A + (size_t)NN * FEAT, 0, (size_t)(MPAD - NN) * FEAT * sizeof(__half));
    }
    // ---- layer 1: input A fp16 [MPAD, 256] ----
    {
        int K = FEAT;
        conv_b_f16<<<(512 * K + 255) / 256, 256>>>(Ws[1], Wd[1], B, K);
        concat_bias<<<1, 512>>>(bs[1], bd[1], bias);
        gemm_mma<<<ggrid, 512, SMEM_GEMM>>>(A, B, bias, ff, K);
        edge_agg<true><<<aggBlocks, 256>>>(ff, attn[1], off, esrc, A, nullptr, 8);
    }
    // ---- layer 2: heads=1 fout=256 -> G=32, fp32 output for head ----
    {
        int K = FEAT;
        conv_b_f16<<<(512 * K + 255) / 256, 256>>>(Ws[2], Wd[2], B, K);
        concat_bias<<<1, 512>>>(bs[2], bd[2], bias);
        gemm_mma<<<ggrid, 512, SMEM_GEMM>>>(A, B, bias, ff, K);
        edge_agg<false><<<aggBlocks, 256>>>(ff, attn[2], off, esrc, nullptr, h, 32);
    }

    // ---- head ----
    build_combined<<<(BATCH * 1024 + 255) / 256, 256>>>(h, pooled, aidx, comb);
    head_mlp<<<BATCH, 256>>>(comb, Wc1, bc1, z1, 1024, 0);
    head_mlp<<<BATCH, 256>>>(z1,   Wc2, bc2, z2, 256, 1);
    head_mlp<<<BATCH, 256>>>(z2,   Wc3, bc3, out, 256, 0);
}

// round 14
// speedup vs baseline: 2.8416x; 1.0890x over previous
#include <cuda_runtime.h>
#include <cuda_fp16.h>
#include <math_constants.h>
#include <cstdint>

// ---------------- problem constants ----------------
#define NN 50000
#define NE 800000
#define FEAT 256
#define INDIM 768
#define BATCH 128
#define ASP 4
#define SLOPE 0.2f

#define MPAD 50048        // 391 * 128
#define FFS 512           // fused fs|fd row stride

// ---------------- static device scratch ----------------
__device__ __half g_a [(size_t)MPAD * INDIM];    // GEMM A (fp16): layer0 K=768, layers1/2 K=256
__device__ __half g_b [(size_t)512 * INDIM];     // GEMM B^T (fp16) [512, K]
__device__ __half g_ff[(size_t)MPAD * FFS];      // fused [fs | fd] fp16
__device__ float  g_h [(size_t)NN * FEAT];       // layer-2 output (fp32 for head)
__device__ float  g_bias[512];
__device__ int    g_deg[NN];
__device__ int    g_off[NN + 1];
__device__ int    g_cur[NN];
__device__ int    g_esrc[NE];
__device__ float  g_comb[BATCH * 1024];
__device__ float  g_z1[BATCH * 256];
__device__ float  g_z2[BATCH * 256];

__device__ __forceinline__ uint32_t smem_u32(const void* p) {
    uint32_t a;
    asm("{ .reg .u64 t; cvta.to.shared.u64 t, %1; cvt.u32.u64 %0, t; }" : "=r"(a) : "l"(p));
    return a;
}

// ---------------- CSR build ----------------
__global__ void hist_kernel(const int* __restrict__ dst, int* __restrict__ deg) {
    int i = blockIdx.x * blockDim.x + threadIdx.x;
    if (i < NE) atomicAdd(&deg[dst[i]], 1);
}

// 1024-thread shuffle-based chunked exclusive scan
__global__ void scan_kernel(const int* __restrict__ deg, int* __restrict__ off,
                            int* __restrict__ cur) {
    __shared__ int wsum[32];
    __shared__ int carry;
    const int tid = threadIdx.x;
    const int lane = tid & 31, wid = tid >> 5;
    if (tid == 0) carry = 0;
    __syncthreads();
    for (int base = 0; base < NN; base += 1024) {
        int i = base + tid;
        int v = (i < NN) ? deg[i] : 0;
        int x = v;
        #pragma unroll
        for (int s = 1; s < 32; s <<= 1) {
            int t = __shfl_up_sync(0xffffffffu, x, s);
            if (lane >= s) x += t;
        }
        if (lane == 31) wsum[wid] = x;
        __syncthreads();
        if (wid == 0) {
            int y = wsum[lane];
            #pragma unroll
            for (int s = 1; s < 32; s <<= 1) {
                int t = __shfl_up_sync(0xffffffffu, y, s);
                if (lane >= s) y += t;
            }
            wsum[lane] = y;
        }
        __syncthreads();
        int incl = x + (wid ? wsum[wid - 1] : 0);
        int excl = carry + incl - v;
        if (i < NN) { off[i] = excl; cur[i] = excl; }
        __syncthreads();
        if (tid == 0) carry += wsum[31];
        __syncthreads();
    }
    if (tid == 0) off[NN] = carry;
}

__global__ void scatter_kernel(const int* __restrict__ src, const int* __restrict__ dst,
                               int* __restrict__ cur, int* __restrict__ esrc) {
    int i = blockIdx.x * blockDim.x + threadIdx.x;
    if (i < NE) {
        int pos = atomicAdd(&cur[dst[i]], 1);
        esrc[pos] = src[i];
    }
}

// ---------------- fp16 conversions ----------------
// A = fp16(X) [MPAD x K], pad rows zero (layer 0 only)
__global__ void conv_a_f16(const float* __restrict__ X, __half* __restrict__ A,
                           int M, int K) {
    int i = blockIdx.x * blockDim.x + threadIdx.x;
    int q = K >> 2;
    if (i >= MPAD * q) return;
    int row = i / q, c4 = (i - row * q) * 4;
    float4 v = make_float4(0.f, 0.f, 0.f, 0.f);
    if (row < M) v = *(const float4*)(X + (size_t)row * K + c4);
    __half2 h0 = __floats2half2_rn(v.x, v.y);
    __half2 h1 = __floats2half2_rn(v.z, v.w);
    uint2 pk;
    pk.x = *(uint32_t*)&h0;
    pk.y = *(uint32_t*)&h1;
    *(uint2*)(A + (size_t)row * K + c4) = pk;
}

// B[n][k] = fp16(W(k, n)) ; n<256 from Ws else Wd (both [K,256])
__global__ void conv_b_f16(const float* __restrict__ Ws, const float* __restrict__ Wd,
                           __half* __restrict__ B, int K) {
    int i = blockIdx.x * blockDim.x + threadIdx.x;
    if (i >= 512 * K) return;
    int n = i / K, k = i - n * K;
    float w = (n < 256) ? Ws[(size_t)k * 256 + n] : Wd[(size_t)k * 256 + (n - 256)];
    B[(size_t)n * K + k] = __float2half_rn(w);
}

__global__ void concat_bias(const float* __restrict__ bs, const float* __restrict__ bd,
                            float* __restrict__ bias) {
    int j = threadIdx.x;
    bias[j] = (j < 256) ? bs[j] : bd[j - 256];
}

// ---------------- mma.sync fp16 GEMM: C[MPAD,512](fp16) = A[MPAD,K] @ B[512,K]^T + bias ----------------
// CTA tile 128x256, BK=32, 512 threads (16 warps, warp tile 32x64), 3-stage cp.async.
#define BM 128
#define BN 256
#define BK 32
#define ROWB 80
#define ASM_BYTES (BM * ROWB)
#define BSM_BYTES (BN * ROWB)
#define BUF_BYTES (ASM_BYTES + BSM_BYTES)
#define NSTAGE 3
#define SMEM_GEMM (NSTAGE * BUF_BYTES)   // 92160

__global__ void __launch_bounds__(512, 1)
gemm_mma(const __half* __restrict__ A, const __half* __restrict__ B,
         const float* __restrict__ bias, __half* __restrict__ C, int K) {
    extern __shared__ char smem[];
    const uint32_t sb = smem_u32(smem);
    const int tid = threadIdx.x;
    const int wid = tid >> 5, lane = tid & 31;
    const int wm = (wid & 3) * 32;
    const int wn = (wid >> 2) * 64;
    const int m0 = blockIdx.y * BM;
    const int n0 = blockIdx.x * BN;
    const int NC = K / BK;

    float acc[2][8][4];
    #pragma unroll
    for (int i = 0; i < 2; i++)
        #pragma unroll
        for (int j = 0; j < 8; j++)
            #pragma unroll
            for (int q = 0; q < 4; q++) acc[i][j][q] = 0.f;

    const int ar = tid >> 2, ac = tid & 3;
    const int br0 = tid >> 1, bc0 = (tid & 1) * 2;

    #define ISSUE(kc, buf) do {                                                        \
        int _col = (kc) * BK;                                                          \
        uint32_t _ab = sb + (buf) * BUF_BYTES;                                         \
        uint32_t _bb = _ab + ASM_BYTES;                                                \
        {                                                                              \
            uint32_t s = _ab + ar * ROWB + ac * 16;                                    \
            const char* g = (const char*)(A + (size_t)(m0 + ar) * K + _col) + ac * 16; \
            asm volatile("cp.async.cg.shared.global [%0], [%1], 16;" :: "r"(s), "l"(g)); \
        }                                                                              \
        _Pragma("unroll")                                                              \
        for (int _i = 0; _i < 2; _i++) {                                               \
            int _c = bc0 + _i;                                                         \
            uint32_t s = _bb + br0 * ROWB + _c * 16;                                   \
            const char* g = (const char*)(B + (size_t)(n0 + br0) * K + _col) + _c * 16; \
            asm volatile("cp.async.cg.shared.global [%0], [%1], 16;" :: "r"(s), "l"(g)); \
        }                                                                              \
        asm volatile("cp.async.commit_group;");                                        \
    } while (0)

    ISSUE(0, 0);
    if (NC > 1) ISSUE(1, 1);

    for (int kc = 0; kc < NC; kc++) {
        int buf = kc % NSTAGE;
        if (kc + 2 < NC) {
            ISSUE(kc + 2, (kc + 2) % NSTAGE);
            asm volatile("cp.async.wait_group 2;");
        } else if (kc + 1 < NC) {
            asm volatile("cp.async.wait_group 1;");
        } else {
            asm volatile("cp.async.wait_group 0;");
        }
        __syncthreads();

        uint32_t ab = sb + buf * BUF_BYTES;
        uint32_t bb = ab + ASM_BYTES;
        #pragma unroll
        for (int ks = 0; ks < 2; ks++) {
            uint32_t a[2][4], b[4][4];
            #pragma unroll
            for (int mi = 0; mi < 2; mi++) {
                uint32_t addr = ab + (uint32_t)(wm + mi * 16 + (lane & 15)) * ROWB
                              + (uint32_t)(ks * 32 + (lane >> 4) * 16);
                asm volatile("ldmatrix.sync.aligned.m8n8.x4.shared.b16 {%0,%1,%2,%3}, [%4];"
                    : "=r"(a[mi][0]), "=r"(a[mi][1]), "=r"(a[mi][2]), "=r"(a[mi][3])
                    : "r"(addr));
            }
            #pragma unroll
            for (int nb = 0; nb < 4; nb++) {
                int n = wn + nb * 16 + ((lane >> 4) << 3) + (lane & 7);
                int k = ks * 16 + (((lane >> 3) & 1) << 3);
                uint32_t addr = bb + (uint32_t)n * ROWB + (uint32_t)k * 2;
                asm volatile("ldmatrix.sync.aligned.m8n8.x4.shared.b16 {%0,%1,%2,%3}, [%4];"
                    : "=r"(b[nb][0]), "=r"(b[nb][1]), "=r"(b[nb][2]), "=r"(b[nb][3])
                    : "r"(addr));
            }
            #pragma unroll
            for (int mi = 0; mi < 2; mi++)
                #pragma unroll
                for (int ni = 0; ni < 8; ni++) {
                    asm volatile(
                        "mma.sync.aligned.m16n8k16.row.col.f32.f16.f16.f32 "
                        "{%0,%1,%2,%3}, {%4,%5,%6,%7}, {%8,%9}, {%0,%1,%2,%3};"
                        : "+f"(acc[mi][ni][0]), "+f"(acc[mi][ni][1]),
                          "+f"(acc[mi][ni][2]), "+f"(acc[mi][ni][3])
                        : "r"(a[mi][0]), "r"(a[mi][1]), "r"(a[mi][2]), "r"(a[mi][3]),
                          "r"(b[ni >> 1][(ni & 1) * 2]), "r"(b[ni >> 1][(ni & 1) * 2 + 1]));
                }
        }
        __syncthreads();
    }
    #undef ISSUE

    // epilogue: fp16 out
    #pragma unroll
    for (int mi = 0; mi < 2; mi++) {
        int r0 = m0 + wm + mi * 16 + (lane >> 2);
        #pragma unroll
        for (int ni = 0; ni < 8; ni++) {
            int col = n0 + wn + ni * 8 + (lane & 3) * 2;
            float bx = bias[col], by = bias[col + 1];
            __half2 v0 = __floats2half2_rn(acc[mi][ni][0] + bx, acc[mi][ni][1] + by);
            __half2 v1 = __floats2half2_rn(acc[mi][ni][2] + bx, acc[mi][ni][3] + by);
            *(__half2*)(C + (size_t)r0 * FFS + col) = v0;
            *(__half2*)(C + (size_t)(r0 + 8) * FFS + col) = v1;
        }
    }
}

// ---------------- fused GATv2 edge stage (fp16 ff rows: fs at +0, fd at +256) ----------------
__device__ __forceinline__ void load8h(const __half* p, float* out) {
    uint4 w = *(const uint4*)p;
    const __half2* hp = (const __half2*)&w;
    float2 f0 = __half22float2(hp[0]);
    float2 f1 = __half22float2(hp[1]);
    float2 f2 = __half22float2(hp[2]);
    float2 f3 = __half22float2(hp[3]);
    out[0] = f0.x; out[1] = f0.y; out[2] = f1.x; out[3] = f1.y;
    out[4] = f2.x; out[5] = f2.y; out[6] = f3.x; out[7] = f3.y;
}

template <bool OUT_HALF>
__global__ void __launch_bounds__(256)
edge_agg(const __half* __restrict__ ff, const float* __restrict__ attn,
         const int* __restrict__ off, const int* __restrict__ esrc,
         __half* __restrict__ outh, float* __restrict__ outf, int G) {
    int warp = (blockIdx.x * blockDim.x + threadIdx.x) >> 5;
    int lane = threadIdx.x & 31;
    if (warp >= NN) return;
    const int v = warp;
    const int s0 = off[v], s1 = off[v + 1];

    float fdv[8];
    load8h(ff + (size_t)v * FFS + 256 + lane * 8, fdv);
    float4 a0 = *(const float4*)(attn + lane * 8);
    float4 a1 = *(const float4*)(attn + lane * 8 + 4);
    float at[8] = {a0.x, a0.y, a0.z, a0.w, a1.x, a1.y, a1.z, a1.w};

    float m = -CUDART_INF_F, d = 0.f;
    float acc[8];
    #pragma unroll
    for (int j = 0; j < 8; j++) acc[j] = 0.f;

    int p = s0;
    // 2-way unrolled main loop: two independent gathers + interleaved reductions
    for (; p + 2 <= s1; p += 2) {
        int u0 = esrc[p];
        int u1 = esrc[p + 1];
        float f0[8], f1[8];
        load8h(ff + (size_t)u0 * FFS + lane * 8, f0);
        load8h(ff + (size_t)u1 * FFS + lane * 8, f1);
        float p0 = 0.f, p1 = 0.f;
        #pragma unroll
        for (int j = 0; j < 8; j++) {
            float e0 = f0[j] + fdv[j];
            float e1 = f1[j] + fdv[j];
            float l0 = (e0 > 0.f) ? e0 : SLOPE * e0;
            float l1 = (e1 > 0.f) ? e1 : SLOPE * e1;
            p0 += l0 * at[j];
            p1 += l1 * at[j];
        }
        #pragma unroll
        for (int sh = 1; sh < 32; sh <<= 1) {
            if (sh < G) {
                p0 += __shfl_xor_sync(0xffffffffu, p0, sh);
                p1 += __shfl_xor_sync(0xffffffffu, p1, sh);
            }
        }
        float nm = fmaxf(m, fmaxf(p0, p1));
        float scale = __expf(m - nm);
        float w0 = __expf(p0 - nm);
        float w1 = __expf(p1 - nm);
        d = d * scale + w0 + w1;
        #pragma unroll
        for (int j = 0; j < 8; j++)
            acc[j] = acc[j] * scale + w0 * f0[j] + w1 * f1[j];
        m = nm;
    }
    // tail (0 or 1 edge)
    if (p < s1) {
        int u = esrc[p];
        float fsu[8];
        load8h(ff + (size_t)u * FFS + lane * 8, fsu);
        float partial = 0.f;
        #pragma unroll
        for (int j = 0; j < 8; j++) {
            float e = fsu[j] + fdv[j];
            float el = (e > 0.f) ? e : SLOPE * e;
            partial += el * at[j];
        }
        #pragma unroll
        for (int sh = 1; sh < 32; sh <<= 1)
            if (sh < G) partial += __shfl_xor_sync(0xffffffffu, partial, sh);
        float nm = fmaxf(m, partial);
        float scale = __expf(m - nm);
        float w = __expf(partial - nm);
        d = d * scale + w;
        #pragma unroll
        for (int j = 0; j < 8; j++) acc[j] = acc[j] * scale + w * fsu[j];
        m = nm;
    }

    float inv = (s1 > s0) ? (1.f / d) : 0.f;
    if (OUT_HALF) {
        __half2 h[4];
        #pragma unroll
        for (int j = 0; j < 4; j++)
            h[j] = __floats2half2_rn(acc[2 * j] * inv, acc[2 * j + 1] * inv);
        *(uint4*)(outh + (size_t)v * FEAT + lane * 8) = *(uint4*)h;
    } else {
        float* op = outf + (size_t)v * FEAT + lane * 8;
        float4 o0, o1;
        o0.x = acc[0] * inv; o0.y = acc[1] * inv; o0.z = acc[2] * inv; o0.w = acc[3] * inv;
        o1.x = acc[4] * inv; o1.y = acc[5] * inv; o1.z = acc[6] * inv; o1.w = acc[7] * inv;
        *(float4*)(op) = o0;
        *(float4*)(op + 4) = o1;
    }
}

// ---------------- head ----------------
__global__ void build_combined(const float* __restrict__ h, const float* __restrict__ pooled,
                               const int* __restrict__ aidx, float* __restrict__ comb) {
    int i = blockIdx.x * blockDim.x + threadIdx.x;
    if (i >= BATCH * 1024) return;
    int b = i >> 10, j = i & 1023;
    if (j < 256) {
        float s = 0.f;
        #pragma unroll
        for (int a = 0; a < ASP; a++) {
            int node = aidx[b * ASP + a];
            s += h[(size_t)node * FEAT + j];
        }
        comb[i] = 0.25f * s;
    } else {
        comb[i] = pooled[(size_t)b * INDIM + (j - 256)];
    }
}

__global__ void __launch_bounds__(256)
head_mlp(const float* __restrict__ in, const float* __restrict__ W,
         const float* __restrict__ bias, float* __restrict__ out, int K, int relu) {
    __shared__ float row[1024];
    int b = blockIdx.x, j = threadIdx.x;
    for (int k = j; k < K; k += 256) row[k] = in[(size_t)b * K + k];
    __syncthreads();
    float sum = bias[j];
    for (int k = 0; k < K; k++) sum += row[k] * W[(size_t)k * 256 + j];
    if (relu) sum = fmaxf(sum, 0.f);
    out[(size_t)b * 256 + j] = sum;
}

// ---------------- launch ----------------
extern "C" void kernel_launch(void* const* d_in, const int* in_sizes, int n_in,
                              void* d_out, int out_size) {
    const float* x      = (const float*)d_in[0];
    const float* pooled = (const float*)d_in[1];
    const int*   src    = (const int*)d_in[2];
    const int*   dst    = (const int*)d_in[3];
    const int*   aidx   = (const int*)d_in[4];
    const float* Ws[3]  = {(const float*)d_in[5],  (const float*)d_in[10], (const float*)d_in[15]};
    const float* bs[3]  = {(const float*)d_in[6],  (const float*)d_in[11], (const float*)d_in[16]};
    const float* Wd[3]  = {(const float*)d_in[7],  (const float*)d_in[12], (const float*)d_in[17]};
    const float* bd[3]  = {(const float*)d_in[8],  (const float*)d_in[13], (const float*)d_in[18]};
    const float* attn[3]= {(const float*)d_in[9],  (const float*)d_in[14], (const float*)d_in[19]};
    const float* Wc1 = (const float*)d_in[20]; const float* bc1 = (const float*)d_in[21];
    const float* Wc2 = (const float*)d_in[22]; const float* bc2 = (const float*)d_in[23];
    const float* Wc3 = (const float*)d_in[24]; const float* bc3 = (const float*)d_in[25];
    float* out = (float*)d_out;

    __half *A, *B, *ff;
    float *h, *bias, *comb, *z1, *z2;
    int *deg, *off, *cur, *esrc;
    cudaGetSymbolAddress((void**)&A,    g_a);
    cudaGetSymbolAddress((void**)&B,    g_b);
    cudaGetSymbolAddress((void**)&ff,   g_ff);
    cudaGetSymbolAddress((void**)&h,    g_h);
    cudaGetSymbolAddress((void**)&bias, g_bias);
    cudaGetSymbolAddress((void**)&deg,  g_deg);
    cudaGetSymbolAddress((void**)&off,  g_off);
    cudaGetSymbolAddress((void**)&cur,  g_cur);
    cudaGetSymbolAddress((void**)&esrc, g_esrc);
    cudaGetSymbolAddress((void**)&comb, g_comb);
    cudaGetSymbolAddress((void**)&z1,   g_z1);
    cudaGetSymbolAddress((void**)&z2,   g_z2);

    cudaFuncSetAttribute(gemm_mma, cudaFuncAttributeMaxDynamicSharedMemorySize, SMEM_GEMM);

    dim3 ggrid(512 / BN, MPAD / BM);   // (2, 391)
    const int aggBlocks = (NN * 32 + 255) / 256;

    // ---- layer 0 prologue first, so the 5th GPU op is gemm_mma(K=768) for ncu ----
    conv_a_f16<<<(MPAD * (INDIM / 4) + 255) / 256, 256>>>(x, A, NN, INDIM);       // 1
    conv_b_f16<<<(512 * INDIM + 255) / 256, 256>>>(Ws[0], Wd[0], B, INDIM);       // 2
    concat_bias<<<1, 512>>>(bs[0], bd[0], bias);                                  // 3
    cudaMemsetAsync(deg, 0, NN * sizeof(int));                                    // 4
    gemm_mma<<<ggrid, 512, SMEM_GEMM>>>(A, B, bias, ff, INDIM);                   // 5 <- profiled

    // ---- CSR build (independent of gemm; must finish before edge_agg) ----
    hist_kernel<<<(NE + 255) / 256, 256>>>(dst, deg);
    scan_kernel<<<1, 1024>>>(deg, off, cur);
    scatter_kernel<<<(NE + 255) / 256, 256>>>(src, dst, cur, esrc);

    // ---- layer 0 edge stage ----
    edge_agg<true><<<aggBlocks, 256>>>(ff, attn[0], off, esrc, A, nullptr, 8);
    cudaMemsetAsync(A + (size_t)NN * FEAT, 0, (size_t)(MPAD - NN) * FEAT * sizeof(__half));

    // ---- layer 1: input A fp16 [MPAD, 256] ----
    {
        int K = FEAT;
        conv_b_f16<<<(512 * K + 255) / 256, 256>>>(Ws[1], Wd[1], B, K);
        concat_bias<<<1, 512>>>(bs[1], bd[1], bias);
        gemm_mma<<<ggrid, 512, SMEM_GEMM>>>(A, B, bias, ff, K);
        edge_agg<true><<<aggBlocks, 256>>>(ff, attn[1], off, esrc, A, nullptr, 8);
    }
    // ---- layer 2: heads=1 fout=256 -> G=32, fp32 output for head ----
    {
        int K = FEAT;
        conv_b_f16<<<(512 * K + 255) / 256, 256>>>(Ws[2], Wd[2], B, K);
        concat_bias<<<1, 512>>>(bs[2], bd[2], bias);
        gemm_mma<<<ggrid, 512, SMEM_GEMM>>>(A, B, bias, ff, K);
        edge_agg<false><<<aggBlocks, 256>>>(ff, attn[2], off, esrc, nullptr, h, 32);
    }

    // ---- head ----
    build_combined<<<(BATCH * 1024 + 255) / 256, 256>>>(h, pooled, aidx, comb);
    head_mlp<<<BATCH, 256>>>(comb, Wc1, bc1, z1, 1024, 0);
    head_mlp<<<BATCH, 256>>>(z1,   Wc2, bc2, z2, 256, 1);
    head_mlp<<<BATCH, 256>>>(z2,   Wc3, bc3, out, 256, 0);
}

// round 15
// speedup vs baseline: 3.0750x; 1.0821x over previous
#include <cuda_runtime.h>
#include <cuda_fp16.h>
#include <math_constants.h>
#include <cstdint>

// ---------------- problem constants ----------------
#define NN 50000
#define NE 800000
#define FEAT 256
#define INDIM 768
#define BATCH 128
#define ASP 4
#define SLOPE 0.2f

#define MPAD 50048        // 391 * 128
#define FFS 512           // fused fs|fd row stride

// ---------------- static device scratch ----------------
__device__ __half g_a [(size_t)MPAD * INDIM];    // GEMM A (fp16): layer0 K=768, layers1/2 K=256
__device__ __half g_b [(size_t)512 * INDIM];     // GEMM B^T (fp16) [512, K]
__device__ __half g_ff[(size_t)MPAD * FFS];      // fused [fs | fd] fp16
__device__ float  g_h [(size_t)NN * FEAT];       // layer-2 output (fp32 for head)
__device__ float  g_bias[512];
__device__ int    g_deg[NN];
__device__ int    g_off[NN + 1];
__device__ int    g_cur[NN];
__device__ int    g_esrc[NE];
__device__ float  g_comb[BATCH * 1024];
__device__ float  g_z1[BATCH * 256];
__device__ float  g_z2[BATCH * 256];

__device__ __forceinline__ uint32_t smem_u32(const void* p) {
    uint32_t a;
    asm("{ .reg .u64 t; cvta.to.shared.u64 t, %1; cvt.u32.u64 %0, t; }" : "=r"(a) : "l"(p));
    return a;
}

// ---------------- CSR build ----------------
__global__ void hist_kernel(const int* __restrict__ dst, int* __restrict__ deg) {
    int i = blockIdx.x * blockDim.x + threadIdx.x;
    if (i < NE) atomicAdd(&deg[dst[i]], 1);
}

// 1024-thread shuffle-based chunked exclusive scan
__global__ void scan_kernel(const int* __restrict__ deg, int* __restrict__ off,
                            int* __restrict__ cur) {
    __shared__ int wsum[32];
    __shared__ int carry;
    const int tid = threadIdx.x;
    const int lane = tid & 31, wid = tid >> 5;
    if (tid == 0) carry = 0;
    __syncthreads();
    for (int base = 0; base < NN; base += 1024) {
        int i = base + tid;
        int v = (i < NN) ? deg[i] : 0;
        int x = v;
        #pragma unroll
        for (int s = 1; s < 32; s <<= 1) {
            int t = __shfl_up_sync(0xffffffffu, x, s);
            if (lane >= s) x += t;
        }
        if (lane == 31) wsum[wid] = x;
        __syncthreads();
        if (wid == 0) {
            int y = wsum[lane];
            #pragma unroll
            for (int s = 1; s < 32; s <<= 1) {
                int t = __shfl_up_sync(0xffffffffu, y, s);
                if (lane >= s) y += t;
            }
            wsum[lane] = y;
        }
        __syncthreads();
        int incl = x + (wid ? wsum[wid - 1] : 0);
        int excl = carry + incl - v;
        if (i < NN) { off[i] = excl; cur[i] = excl; }
        __syncthreads();
        if (tid == 0) carry += wsum[31];
        __syncthreads();
    }
    if (tid == 0) off[NN] = carry;
}

__global__ void scatter_kernel(const int* __restrict__ src, const int* __restrict__ dst,
                               int* __restrict__ cur, int* __restrict__ esrc) {
    int i = blockIdx.x * blockDim.x + threadIdx.x;
    if (i < NE) {
        int pos = atomicAdd(&cur[dst[i]], 1);
        esrc[pos] = src[i];
    }
}

// ---------------- fp16 conversions ----------------
// A = fp16(X) [MPAD x K], pad rows zero (layer 0 only)
__global__ void conv_a_f16(const float* __restrict__ X, __half* __restrict__ A,
                           int M, int K) {
    int i = blockIdx.x * blockDim.x + threadIdx.x;
    int q = K >> 2;
    if (i >= MPAD * q) return;
    int row = i / q, c4 = (i - row * q) * 4;
    float4 v = make_float4(0.f, 0.f, 0.f, 0.f);
    if (row < M) v = *(const float4*)(X + (size_t)row * K + c4);
    __half2 h0 = __floats2half2_rn(v.x, v.y);
    __half2 h1 = __floats2half2_rn(v.z, v.w);
    uint2 pk;
    pk.x = *(uint32_t*)&h0;
    pk.y = *(uint32_t*)&h1;
    *(uint2*)(A + (size_t)row * K + c4) = pk;
}

// B[n][k] = fp16(W(k, n)) ; n<256 from Ws else Wd (both [K,256])
__global__ void conv_b_f16(const float* __restrict__ Ws, const float* __restrict__ Wd,
                           __half* __restrict__ B, int K) {
    int i = blockIdx.x * blockDim.x + threadIdx.x;
    if (i >= 512 * K) return;
    int n = i / K, k = i - n * K;
    float w = (n < 256) ? Ws[(size_t)k * 256 + n] : Wd[(size_t)k * 256 + (n - 256)];
    B[(size_t)n * K + k] = __float2half_rn(w);
}

__global__ void concat_bias(const float* __restrict__ bs, const float* __restrict__ bd,
                            float* __restrict__ bias) {
    int j = threadIdx.x;
    bias[j] = (j < 256) ? bs[j] : bd[j - 256];
}

// ---------------- mma.sync fp16 GEMM: C[MPAD,512](fp16) = A[MPAD,K] @ B[512,K]^T + bias ----------------
// CTA tile 128x128, BK=32, 256 threads (8 warps, warp tile 32x64), 3-stage cp.async,
// 2 CTAs/SM so barrier phases in one CTA overlap compute in the other.
#define BM 128
#define BN 128
#define BK 32
#define ROWB 80
#define ASM_BYTES (BM * ROWB)            // 10240
#define BSM_BYTES (BN * ROWB)            // 10240
#define BUF_BYTES (ASM_BYTES + BSM_BYTES)
#define NSTAGE 3
#define SMEM_GEMM (NSTAGE * BUF_BYTES)   // 61440

__global__ void __launch_bounds__(256, 2)
gemm_mma(const __half* __restrict__ A, const __half* __restrict__ B,
         const float* __restrict__ bias, __half* __restrict__ C, int K) {
    extern __shared__ char smem[];
    const uint32_t sb = smem_u32(smem);
    const int tid = threadIdx.x;
    const int wid = tid >> 5, lane = tid & 31;
    const int wm = (wid & 3) * 32;
    const int wn = (wid >> 2) * 64;
    const int m0 = blockIdx.y * BM;
    const int n0 = blockIdx.x * BN;
    const int NC = K / BK;

    float acc[2][8][4];
    #pragma unroll
    for (int i = 0; i < 2; i++)
        #pragma unroll
        for (int j = 0; j < 8; j++)
            #pragma unroll
            for (int q = 0; q < 4; q++) acc[i][j][q] = 0.f;

    // per-thread load coords: 2 threads/row, 2 x 16B chunks each (row = 64B)
    const int ar = tid >> 1, ac0 = (tid & 1) * 2;

    #define ISSUE(kc, buf) do {                                                        \
        int _col = (kc) * BK;                                                          \
        uint32_t _ab = sb + (buf) * BUF_BYTES;                                         \
        uint32_t _bb = _ab + ASM_BYTES;                                                \
        _Pragma("unroll")                                                              \
        for (int _i = 0; _i < 2; _i++) {                                               \
            int _c = ac0 + _i;                                                         \
            uint32_t s = _ab + ar * ROWB + _c * 16;                                    \
            const char* g = (const char*)(A + (size_t)(m0 + ar) * K + _col) + _c * 16; \
            asm volatile("cp.async.cg.shared.global [%0], [%1], 16;" :: "r"(s), "l"(g)); \
        }                                                                              \
        _Pragma("unroll")                                                              \
        for (int _i = 0; _i < 2; _i++) {                                               \
            int _c = ac0 + _i;                                                         \
            uint32_t s = _bb + ar * ROWB + _c * 16;                                    \
            const char* g = (const char*)(B + (size_t)(n0 + ar) * K + _col) + _c * 16; \
            asm volatile("cp.async.cg.shared.global [%0], [%1], 16;" :: "r"(s), "l"(g)); \
        }                                                                              \
        asm volatile("cp.async.commit_group;");                                        \
    } while (0)

    ISSUE(0, 0);
    if (NC > 1) ISSUE(1, 1);

    for (int kc = 0; kc < NC; kc++) {
        int buf = kc % NSTAGE;
        if (kc + 2 < NC) {
            ISSUE(kc + 2, (kc + 2) % NSTAGE);
            asm volatile("cp.async.wait_group 2;");
        } else if (kc + 1 < NC) {
            asm volatile("cp.async.wait_group 1;");
        } else {
            asm volatile("cp.async.wait_group 0;");
        }
        __syncthreads();

        uint32_t ab = sb + buf * BUF_BYTES;
        uint32_t bb = ab + ASM_BYTES;
        #pragma unroll
        for (int ks = 0; ks < 2; ks++) {
            uint32_t a[2][4], b[4][4];
            #pragma unroll
            for (int mi = 0; mi < 2; mi++) {
                uint32_t addr = ab + (uint32_t)(wm + mi * 16 + (lane & 15)) * ROWB
                              + (uint32_t)(ks * 32 + (lane >> 4) * 16);
                asm volatile("ldmatrix.sync.aligned.m8n8.x4.shared.b16 {%0,%1,%2,%3}, [%4];"
                    : "=r"(a[mi][0]), "=r"(a[mi][1]), "=r"(a[mi][2]), "=r"(a[mi][3])
                    : "r"(addr));
            }
            #pragma unroll
            for (int nb = 0; nb < 4; nb++) {
                int n = wn + nb * 16 + ((lane >> 4) << 3) + (lane & 7);
                int k = ks * 16 + (((lane >> 3) & 1) << 3);
                uint32_t addr = bb + (uint32_t)n * ROWB + (uint32_t)k * 2;
                asm volatile("ldmatrix.sync.aligned.m8n8.x4.shared.b16 {%0,%1,%2,%3}, [%4];"
                    : "=r"(b[nb][0]), "=r"(b[nb][1]), "=r"(b[nb][2]), "=r"(b[nb][3])
                    : "r"(addr));
            }
            #pragma unroll
            for (int mi = 0; mi < 2; mi++)
                #pragma unroll
                for (int ni = 0; ni < 8; ni++) {
                    asm volatile(
                        "mma.sync.aligned.m16n8k16.row.col.f32.f16.f16.f32 "
                        "{%0,%1,%2,%3}, {%4,%5,%6,%7}, {%8,%9}, {%0,%1,%2,%3};"
                        : "+f"(acc[mi][ni][0]), "+f"(acc[mi][ni][1]),
                          "+f"(acc[mi][ni][2]), "+f"(acc[mi][ni][3])
                        : "r"(a[mi][0]), "r"(a[mi][1]), "r"(a[mi][2]), "r"(a[mi][3]),
                          "r"(b[ni >> 1][(ni & 1) * 2]), "r"(b[ni >> 1][(ni & 1) * 2 + 1]));
                }
        }
        __syncthreads();
    }
    #undef ISSUE

    // epilogue: fp16 out
    #pragma unroll
    for (int mi = 0; mi < 2; mi++) {
        int r0 = m0 + wm + mi * 16 + (lane >> 2);
        #pragma unroll
        for (int ni = 0; ni < 8; ni++) {
            int col = n0 + wn + ni * 8 + (lane & 3) * 2;
            float bx = bias[col], by = bias[col + 1];
            __half2 v0 = __floats2half2_rn(acc[mi][ni][0] + bx, acc[mi][ni][1] + by);
            __half2 v1 = __floats2half2_rn(acc[mi][ni][2] + bx, acc[mi][ni][3] + by);
            *(__half2*)(C + (size_t)r0 * FFS + col) = v0;
            *(__half2*)(C + (size_t)(r0 + 8) * FFS + col) = v1;
        }
    }
}

// ---------------- fused GATv2 edge stage (fp16 ff rows: fs at +0, fd at +256) ----------------
__device__ __forceinline__ void load8h(const __half* p, float* out) {
    uint4 w = *(const uint4*)p;
    const __half2* hp = (const __half2*)&w;
    float2 f0 = __half22float2(hp[0]);
    float2 f1 = __half22float2(hp[1]);
    float2 f2 = __half22float2(hp[2]);
    float2 f3 = __half22float2(hp[3]);
    out[0] = f0.x; out[1] = f0.y; out[2] = f1.x; out[3] = f1.y;
    out[4] = f2.x; out[5] = f2.y; out[6] = f3.x; out[7] = f3.y;
}

template <bool OUT_HALF>
__global__ void __launch_bounds__(256)
edge_agg(const __half* __restrict__ ff, const float* __restrict__ attn,
         const int* __restrict__ off, const int* __restrict__ esrc,
         __half* __restrict__ outh, float* __restrict__ outf, int G) {
    int warp = (blockIdx.x * blockDim.x + threadIdx.x) >> 5;
    int lane = threadIdx.x & 31;
    if (warp >= NN) return;
    const int v = warp;
    const int s0 = off[v], s1 = off[v + 1];

    float fdv[8];
    load8h(ff + (size_t)v * FFS + 256 + lane * 8, fdv);
    float4 a0 = *(const float4*)(attn + lane * 8);
    float4 a1 = *(const float4*)(attn + lane * 8 + 4);
    float at[8] = {a0.x, a0.y, a0.z, a0.w, a1.x, a1.y, a1.z, a1.w};

    float m = -CUDART_INF_F, d = 0.f;
    float acc[8];
    #pragma unroll
    for (int j = 0; j < 8; j++) acc[j] = 0.f;

    int p = s0;
    for (; p + 2 <= s1; p += 2) {
        int u0 = esrc[p];
        int u1 = esrc[p + 1];
        float f0[8], f1[8];
        load8h(ff + (size_t)u0 * FFS + lane * 8, f0);
        load8h(ff + (size_t)u1 * FFS + lane * 8, f1);
        float p0 = 0.f, p1 = 0.f;
        #pragma unroll
        for (int j = 0; j < 8; j++) {
            float e0 = f0[j] + fdv[j];
            float e1 = f1[j] + fdv[j];
            float l0 = (e0 > 0.f) ? e0 : SLOPE * e0;
            float l1 = (e1 > 0.f) ? e1 : SLOPE * e1;
            p0 += l0 * at[j];
            p1 += l1 * at[j];
        }
        #pragma unroll
        for (int sh = 1; sh < 32; sh <<= 1) {
            if (sh < G) {
                p0 += __shfl_xor_sync(0xffffffffu, p0, sh);
                p1 += __shfl_xor_sync(0xffffffffu, p1, sh);
            }
        }
        float nm = fmaxf(m, fmaxf(p0, p1));
        float scale = __expf(m - nm);
        float w0 = __expf(p0 - nm);
        float w1 = __expf(p1 - nm);
        d = d * scale + w0 + w1;
        #pragma unroll
        for (int j = 0; j < 8; j++)
            acc[j] = acc[j] * scale + w0 * f0[j] + w1 * f1[j];
        m = nm;
    }
    if (p < s1) {
        int u = esrc[p];
        float fsu[8];
        load8h(ff + (size_t)u * FFS + lane * 8, fsu);
        float partial = 0.f;
        #pragma unroll
        for (int j = 0; j < 8; j++) {
            float e = fsu[j] + fdv[j];
            float el = (e > 0.f) ? e : SLOPE * e;
            partial += el * at[j];
        }
        #pragma unroll
        for (int sh = 1; sh < 32; sh <<= 1)
            if (sh < G) partial += __shfl_xor_sync(0xffffffffu, partial, sh);
        float nm = fmaxf(m, partial);
        float scale = __expf(m - nm);
        float w = __expf(partial - nm);
        d = d * scale + w;
        #pragma unroll
        for (int j = 0; j < 8; j++) acc[j] = acc[j] * scale + w * fsu[j];
        m = nm;
    }

    float inv = (s1 > s0) ? (1.f / d) : 0.f;
    if (OUT_HALF) {
        __half2 h[4];
        #pragma unroll
        for (int j = 0; j < 4; j++)
            h[j] = __floats2half2_rn(acc[2 * j] * inv, acc[2 * j + 1] * inv);
        *(uint4*)(outh + (size_t)v * FEAT + lane * 8) = *(uint4*)h;
    } else {
        float* op = outf + (size_t)v * FEAT + lane * 8;
        float4 o0, o1;
        o0.x = acc[0] * inv; o0.y = acc[1] * inv; o0.z = acc[2] * inv; o0.w = acc[3] * inv;
        o1.x = acc[4] * inv; o1.y = acc[5] * inv; o1.z = acc[6] * inv; o1.w = acc[7] * inv;
        *(float4*)(op) = o0;
        *(float4*)(op + 4) = o1;
    }
}

// ---------------- head ----------------
__global__ void build_combined(const float* __restrict__ h, const float* __restrict__ pooled,
                               const int* __restrict__ aidx, float* __restrict__ comb) {
    int i = blockIdx.x * blockDim.x + threadIdx.x;
    if (i >= BATCH * 1024) return;
    int b = i >> 10, j = i & 1023;
    if (j < 256) {
        float s = 0.f;
        #pragma unroll
        for (int a = 0; a < ASP; a++) {
            int node = aidx[b * ASP + a];
            s += h[(size_t)node * FEAT + j];
        }
        comb[i] = 0.25f * s;
    } else {
        comb[i] = pooled[(size_t)b * INDIM + (j - 256)];
    }
}

__global__ void __launch_bounds__(256)
head_mlp(const float* __restrict__ in, const float* __restrict__ W,
         const float* __restrict__ bias, float* __restrict__ out, int K, int relu) {
    __shared__ float row[1024];
    int b = blockIdx.x, j = threadIdx.x;
    for (int k = j; k < K; k += 256) row[k] = in[(size_t)b * K + k];
    __syncthreads();
    float sum = bias[j];
    for (int k = 0; k < K; k++) sum += row[k] * W[(size_t)k * 256 + j];
    if (relu) sum = fmaxf(sum, 0.f);
    out[(size_t)b * 256 + j] = sum;
}

// ---------------- launch ----------------
extern "C" void kernel_launch(void* const* d_in, const int* in_sizes, int n_in,
                              void* d_out, int out_size) {
    const float* x      = (const float*)d_in[0];
    const float* pooled = (const float*)d_in[1];
    const int*   src    = (const int*)d_in[2];
    const int*   dst    = (const int*)d_in[3];
    const int*   aidx   = (const int*)d_in[4];
    const float* Ws[3]  = {(const float*)d_in[5],  (const float*)d_in[10], (const float*)d_in[15]};
    const float* bs[3]  = {(const float*)d_in[6],  (const float*)d_in[11], (const float*)d_in[16]};
    const float* Wd[3]  = {(const float*)d_in[7],  (const float*)d_in[12], (const float*)d_in[17]};
    const float* bd[3]  = {(const float*)d_in[8],  (const float*)d_in[13], (const float*)d_in[18]};
    const float* attn[3]= {(const float*)d_in[9],  (const float*)d_in[14], (const float*)d_in[19]};
    const float* Wc1 = (const float*)d_in[20]; const float* bc1 = (const float*)d_in[21];
    const float* Wc2 = (const float*)d_in[22]; const float* bc2 = (const float*)d_in[23];
    const float* Wc3 = (const float*)d_in[24]; const float* bc3 = (const float*)d_in[25];
    float* out = (float*)d_out;

    __half *A, *B, *ff;
    float *h, *bias, *comb, *z1, *z2;
    int *deg, *off, *cur, *esrc;
    cudaGetSymbolAddress((void**)&A,    g_a);
    cudaGetSymbolAddress((void**)&B,    g_b);
    cudaGetSymbolAddress((void**)&ff,   g_ff);
    cudaGetSymbolAddress((void**)&h,    g_h);
    cudaGetSymbolAddress((void**)&bias, g_bias);
    cudaGetSymbolAddress((void**)&deg,  g_deg);
    cudaGetSymbolAddress((void**)&off,  g_off);
    cudaGetSymbolAddress((void**)&cur,  g_cur);
    cudaGetSymbolAddress((void**)&esrc, g_esrc);
    cudaGetSymbolAddress((void**)&comb, g_comb);
    cudaGetSymbolAddress((void**)&z1,   g_z1);
    cudaGetSymbolAddress((void**)&z2,   g_z2);

    cudaFuncSetAttribute(gemm_mma, cudaFuncAttributeMaxDynamicSharedMemorySize, SMEM_GEMM);

    dim3 ggrid(512 / BN, MPAD / BM);   // (4, 391)
    const int aggBlocks = (NN * 32 + 255) / 256;

    // ---- layer 0 prologue first, so the 5th GPU op is gemm_mma(K=768) for ncu ----
    conv_a_f16<<<(MPAD * (INDIM / 4) + 255) / 256, 256>>>(x, A, NN, INDIM);       // 1
    conv_b_f16<<<(512 * INDIM + 255) / 256, 256>>>(Ws[0], Wd[0], B, INDIM);       // 2
    concat_bias<<<1, 512>>>(bs[0], bd[0], bias);                                  // 3
    cudaMemsetAsync(deg, 0, NN * sizeof(int));                                    // 4
    gemm_mma<<<ggrid, 256, SMEM_GEMM>>>(A, B, bias, ff, INDIM);                   // 5 <- profiled

    // ---- CSR build (independent of gemm; must finish before edge_agg) ----
    hist_kernel<<<(NE + 255) / 256, 256>>>(dst, deg);
    scan_kernel<<<1, 1024>>>(deg, off, cur);
    scatter_kernel<<<(NE + 255) / 256, 256>>>(src, dst, cur, esrc);

    // ---- layer 0 edge stage ----
    edge_agg<true><<<aggBlocks, 256>>>(ff, attn[0], off, esrc, A, nullptr, 8);
    cudaMemsetAsync(A + (size_t)NN * FEAT, 0, (size_t)(MPAD - NN) * FEAT * sizeof(__half));

    // ---- layer 1: input A fp16 [MPAD, 256] ----
    {
        int K = FEAT;
        conv_b_f16<<<(512 * K + 255) / 256, 256>>>(Ws[1], Wd[1], B, K);
        concat_bias<<<1, 512>>>(bs[1], bd[1], bias);
        gemm_mma<<<ggrid, 256, SMEM_GEMM>>>(A, B, bias, ff, K);
        edge_agg<true><<<aggBlocks, 256>>>(ff, attn[1], off, esrc, A, nullptr, 8);
    }
    // ---- layer 2: heads=1 fout=256 -> G=32, fp32 output for head ----
    {
        int K = FEAT;
        conv_b_f16<<<(512 * K + 255) / 256, 256>>>(Ws[2], Wd[2], B, K);
        concat_bias<<<1, 512>>>(bs[2], bd[2], bias);
        gemm_mma<<<ggrid, 256, SMEM_GEMM>>>(A, B, bias, ff, K);
        edge_agg<false><<<aggBlocks, 256>>>(ff, attn[2], off, esrc, nullptr, h, 32);
    }

    // ---- head ----
    build_combined<<<(BATCH * 1024 + 255) / 256, 256>>>(h, pooled, aidx, comb);
    head_mlp<<<BATCH, 256>>>(comb, Wc1, bc1, z1, 1024, 0);
    head_mlp<<<BATCH, 256>>>(z1,   Wc2, bc2, z2, 256, 1);
    head_mlp<<<BATCH, 256>>>(z2,   Wc3, bc3, out, 256, 0);
}

// round 17
// speedup vs baseline: 3.1087x; 1.0110x over previous
#include <cuda_runtime.h>
#include <cuda_fp16.h>
#include <math_constants.h>
#include <cstdint>

// ---------------- problem constants ----------------
#define NN 50000
#define NE 800000
#define FEAT 256
#define INDIM 768
#define BATCH 128
#define ASP 4
#define SLOPE 0.2f

#define MPAD 50048        // 391 * 128
#define FFS 512           // fused fs|fd row stride

// ---------------- static device scratch ----------------
__device__ __half g_a [(size_t)MPAD * INDIM];    // GEMM A (fp16): layer0 K=768, layers1/2 K=256
__device__ __half g_b [(size_t)512 * INDIM];     // GEMM B^T (fp16) [512, K]
__device__ __half g_ff[(size_t)MPAD * FFS];      // fused [fs | fd] fp16
__device__ float  g_h [(size_t)NN * FEAT];       // layer-2 output (fp32 for head)
__device__ float  g_bias[512];
__device__ int    g_deg[NN];
__device__ int    g_off[NN + 1];
__device__ int    g_cur[NN];
__device__ int    g_esrc[NE];
__device__ float  g_comb[BATCH * 1024];
__device__ float  g_z1[BATCH * 256];
__device__ float  g_z2[BATCH * 256];

__device__ __forceinline__ uint32_t smem_u32(const void* p) {
    uint32_t a;
    asm("{ .reg .u64 t; cvta.to.shared.u64 t, %1; cvt.u32.u64 %0, t; }" : "=r"(a) : "l"(p));
    return a;
}

// ---------------- CSR build ----------------
__global__ void hist_kernel(const int* __restrict__ dst, int* __restrict__ deg) {
    int i = blockIdx.x * blockDim.x + threadIdx.x;
    if (i < NE) atomicAdd(&deg[dst[i]], 1);
}

// 1024-thread shuffle-based chunked exclusive scan
__global__ void scan_kernel(const int* __restrict__ deg, int* __restrict__ off,
                            int* __restrict__ cur) {
    __shared__ int wsum[32];
    __shared__ int carry;
    const int tid = threadIdx.x;
    const int lane = tid & 31, wid = tid >> 5;
    if (tid == 0) carry = 0;
    __syncthreads();
    for (int base = 0; base < NN; base += 1024) {
        int i = base + tid;
        int v = (i < NN) ? deg[i] : 0;
        int x = v;
        #pragma unroll
        for (int s = 1; s < 32; s <<= 1) {
            int t = __shfl_up_sync(0xffffffffu, x, s);
            if (lane >= s) x += t;
        }
        if (lane == 31) wsum[wid] = x;
        __syncthreads();
        if (wid == 0) {
            int y = wsum[lane];
            #pragma unroll
            for (int s = 1; s < 32; s <<= 1) {
                int t = __shfl_up_sync(0xffffffffu, y, s);
                if (lane >= s) y += t;
            }
            wsum[lane] = y;
        }
        __syncthreads();
        int incl = x + (wid ? wsum[wid - 1] : 0);
        int excl = carry + incl - v;
        if (i < NN) { off[i] = excl; cur[i] = excl; }
        __syncthreads();
        if (tid == 0) carry += wsum[31];
        __syncthreads();
    }
    if (tid == 0) off[NN] = carry;
}

__global__ void scatter_kernel(const int* __restrict__ src, const int* __restrict__ dst,
                               int* __restrict__ cur, int* __restrict__ esrc) {
    int i = blockIdx.x * blockDim.x + threadIdx.x;
    if (i < NE) {
        int pos = atomicAdd(&cur[dst[i]], 1);
        esrc[pos] = src[i];
    }
}

// ---------------- fp16 conversions ----------------
// A = fp16(X) [MPAD x K], pad rows zero (layer 0 only)
__global__ void conv_a_f16(const float* __restrict__ X, __half* __restrict__ A,
                           int M, int K) {
    int i = blockIdx.x * blockDim.x + threadIdx.x;
    int q = K >> 2;
    if (i >= MPAD * q) return;
    int row = i / q, c4 = (i - row * q) * 4;
    float4 v = make_float4(0.f, 0.f, 0.f, 0.f);
    if (row < M) v = *(const float4*)(X + (size_t)row * K + c4);
    __half2 h0 = __floats2half2_rn(v.x, v.y);
    __half2 h1 = __floats2half2_rn(v.z, v.w);
    uint2 pk;
    pk.x = *(uint32_t*)&h0;
    pk.y = *(uint32_t*)&h1;
    *(uint2*)(A + (size_t)row * K + c4) = pk;
}

// B[n][k] = fp16(W(k, n)) ; n<256 from Ws else Wd (both [K,256])
__global__ void conv_b_f16(const float* __restrict__ Ws, const float* __restrict__ Wd,
                           __half* __restrict__ B, int K) {
    int i = blockIdx.x * blockDim.x + threadIdx.x;
    if (i >= 512 * K) return;
    int n = i / K, k = i - n * K;
    float w = (n < 256) ? Ws[(size_t)k * 256 + n] : Wd[(size_t)k * 256 + (n - 256)];
    B[(size_t)n * K + k] = __float2half_rn(w);
}

__global__ void concat_bias(const float* __restrict__ bs, const float* __restrict__ bd,
                            float* __restrict__ bias) {
    int j = threadIdx.x;
    bias[j] = (j < 256) ? bs[j] : bd[j - 256];
}

// ---------------- mma.sync fp16 GEMM: C[MPAD,512](fp16) = A[MPAD,K] @ B[512,K]^T + bias ----------------
// CTA tile 128x128, BK=32, 256 threads (8 warps, warp tile 32x64), 4-stage cp.async,
// SINGLE __syncthreads per mainloop iteration, 2 CTAs/SM.
#define BM 128
#define BN 128
#define BK 32
#define ROWB 80
#define ASM_BYTES (BM * ROWB)            // 10240
#define BSM_BYTES (BN * ROWB)            // 10240
#define BUF_BYTES (ASM_BYTES + BSM_BYTES)
#define NSTAGE 4
#define SMEM_GEMM (NSTAGE * BUF_BYTES)   // 81920

__global__ void __launch_bounds__(256, 2)
gemm_mma(const __half* __restrict__ A, const __half* __restrict__ B,
         const float* __restrict__ bias, __half* __restrict__ C, int K) {
    extern __shared__ char smem[];
    const uint32_t sb = smem_u32(smem);
    const int tid = threadIdx.x;
    const int wid = tid >> 5, lane = tid & 31;
    const int wm = (wid & 3) * 32;
    const int wn = (wid >> 2) * 64;
    const int m0 = blockIdx.y * BM;
    const int n0 = blockIdx.x * BN;
    const int NC = K / BK;               // >= 8

    float acc[2][8][4];
    #pragma unroll
    for (int i = 0; i < 2; i++)
        #pragma unroll
        for (int j = 0; j < 8; j++)
            #pragma unroll
            for (int q = 0; q < 4; q++) acc[i][j][q] = 0.f;

    // per-thread load coords: 2 threads/row, 2 x 16B chunks each (row = 64B)
    const int ar = tid >> 1, ac0 = (tid & 1) * 2;

    #define ISSUE(kc, buf) do {                                                        \
        int _col = (kc) * BK;                                                          \
        uint32_t _ab = sb + (buf) * BUF_BYTES;                                         \
        uint32_t _bb = _ab + ASM_BYTES;                                                \
        _Pragma("unroll")                                                              \
        for (int _i = 0; _i < 2; _i++) {                                               \
            int _c = ac0 + _i;                                                         \
            uint32_t s = _ab + ar * ROWB + _c * 16;                                    \
            const char* g = (const char*)(A + (size_t)(m0 + ar) * K + _col) + _c * 16; \
            asm volatile("cp.async.cg.shared.global [%0], [%1], 16;" :: "r"(s), "l"(g)); \
        }                                                                              \
        _Pragma("unroll")                                                              \
        for (int _i = 0; _i < 2; _i++) {                                               \
            int _c = ac0 + _i;                                                         \
            uint32_t s = _bb + ar * ROWB + _c * 16;                                    \
            const char* g = (const char*)(B + (size_t)(n0 + ar) * K + _col) + _c * 16; \
            asm volatile("cp.async.cg.shared.global [%0], [%1], 16;" :: "r"(s), "l"(g)); \
        }                                                                              \
        asm volatile("cp.async.commit_group;");                                        \
    } while (0)

    // prologue: prefetch 3 chunks (distance 3, 4 buffers)
    ISSUE(0, 0);
    ISSUE(1, 1);
    ISSUE(2, 2);

    for (int kc = 0; kc < NC; kc++) {
        // wait for chunk kc: groups outstanding beyond kc = min(2, NC-1-kc)
        int rem = NC - 1 - kc;
        if (rem >= 2)      asm volatile("cp.async.wait_group 2;");
        else if (rem == 1) asm volatile("cp.async.wait_group 1;");
        else               asm volatile("cp.async.wait_group 0;");
        __syncthreads();   // publishes chunk kc, retires compute(kc-1) for all warps

        if (kc + 3 < NC) ISSUE(kc + 3, (kc + 3) % NSTAGE);

        uint32_t ab = sb + (kc % NSTAGE) * BUF_BYTES;
        uint32_t bb = ab + ASM_BYTES;
        #pragma unroll
        for (int ks = 0; ks < 2; ks++) {
            uint32_t a[2][4], b[4][4];
            #pragma unroll
            for (int mi = 0; mi < 2; mi++) {
                uint32_t addr = ab + (uint32_t)(wm + mi * 16 + (lane & 15)) * ROWB
                              + (uint32_t)(ks * 32 + (lane >> 4) * 16);
                asm volatile("ldmatrix.sync.aligned.m8n8.x4.shared.b16 {%0,%1,%2,%3}, [%4];"
                    : "=r"(a[mi][0]), "=r"(a[mi][1]), "=r"(a[mi][2]), "=r"(a[mi][3])
                    : "r"(addr));
            }
            #pragma unroll
            for (int nb = 0; nb < 4; nb++) {
                int n = wn + nb * 16 + ((lane >> 4) << 3) + (lane & 7);
                int k = ks * 16 + (((lane >> 3) & 1) << 3);
                uint32_t addr = bb + (uint32_t)n * ROWB + (uint32_t)k * 2;
                asm volatile("ldmatrix.sync.aligned.m8n8.x4.shared.b16 {%0,%1,%2,%3}, [%4];"
                    : "=r"(b[nb][0]), "=r"(b[nb][1]), "=r"(b[nb][2]), "=r"(b[nb][3])
                    : "r"(addr));
            }
            #pragma unroll
            for (int mi = 0; mi < 2; mi++)
                #pragma unroll
                for (int ni = 0; ni < 8; ni++) {
                    asm volatile(
                        "mma.sync.aligned.m16n8k16.row.col.f32.f16.f16.f32 "
                        "{%0,%1,%2,%3}, {%4,%5,%6,%7}, {%8,%9}, {%0,%1,%2,%3};"
                        : "+f"(acc[mi][ni][0]), "+f"(acc[mi][ni][1]),
                          "+f"(acc[mi][ni][2]), "+f"(acc[mi][ni][3])
                        : "r"(a[mi][0]), "r"(a[mi][1]), "r"(a[mi][2]), "r"(a[mi][3]),
                          "r"(b[ni >> 1][(ni & 1) * 2]), "r"(b[ni >> 1][(ni & 1) * 2 + 1]));
                }
        }
        // no trailing barrier: next iteration's top barrier protects buffer reuse
    }
    #undef ISSUE

    // epilogue: fp16 out
    #pragma unroll
    for (int mi = 0; mi < 2; mi++) {
        int r0 = m0 + wm + mi * 16 + (lane >> 2);
        #pragma unroll
        for (int ni = 0; ni < 8; ni++) {
            int col = n0 + wn + ni * 8 + (lane & 3) * 2;
            float bx = bias[col], by = bias[col + 1];
            __half2 v0 = __floats2half2_rn(acc[mi][ni][0] + bx, acc[mi][ni][1] + by);
            __half2 v1 = __floats2half2_rn(acc[mi][ni][2] + bx, acc[mi][ni][3] + by);
            *(__half2*)(C + (size_t)r0 * FFS + col) = v0;
            *(__half2*)(C + (size_t)(r0 + 8) * FFS + col) = v1;
        }
    }
}

// ---------------- fused GATv2 edge stage (fp16 ff rows: fs at +0, fd at +256) ----------------
__device__ __forceinline__ void load8h(const __half* p, float* out) {
    uint4 w = *(const uint4*)p;
    const __half2* hp = (const __half2*)&w;
    float2 f0 = __half22float2(hp[0]);
    float2 f1 = __half22float2(hp[1]);
    float2 f2 = __half22float2(hp[2]);
    float2 f3 = __half22float2(hp[3]);
    out[0] = f0.x; out[1] = f0.y; out[2] = f1.x; out[3] = f1.y;
    out[4] = f2.x; out[5] = f2.y; out[6] = f3.x; out[7] = f3.y;
}

template <bool OUT_HALF>
__global__ void __launch_bounds__(256)
edge_agg(const __half* __restrict__ ff, const float* __restrict__ attn,
         const int* __restrict__ off, const int* __restrict__ esrc,
         __half* __restrict__ outh, float* __restrict__ outf, int G) {
    int warp = (blockIdx.x * blockDim.x + threadIdx.x) >> 5;
    int lane = threadIdx.x & 31;
    if (warp >= NN) return;
    const int v = warp;
    const int s0 = off[v], s1 = off[v + 1];

    float fdv[8];
    load8h(ff + (size_t)v * FFS + 256 + lane * 8, fdv);
    float4 a0 = *(const float4*)(attn + lane * 8);
    float4 a1 = *(const float4*)(attn + lane * 8 + 4);
    float at[8] = {a0.x, a0.y, a0.z, a0.w, a1.x, a1.y, a1.z, a1.w};

    float m = -CUDART_INF_F, d = 0.f;
    float acc[8];
    #pragma unroll
    for (int j = 0; j < 8; j++) acc[j] = 0.f;

    int p = s0;
    for (; p + 2 <= s1; p += 2) {
        int u0 = esrc[p];
        int u1 = esrc[p + 1];
        float f0[8], f1[8];
        load8h(ff + (size_t)u0 * FFS + lane * 8, f0);
        load8h(ff + (size_t)u1 * FFS + lane * 8, f1);
        float p0 = 0.f, p1 = 0.f;
        #pragma unroll
        for (int j = 0; j < 8; j++) {
            float e0 = f0[j] + fdv[j];
            float e1 = f1[j] + fdv[j];
            float l0 = (e0 > 0.f) ? e0 : SLOPE * e0;
            float l1 = (e1 > 0.f) ? e1 : SLOPE * e1;
            p0 += l0 * at[j];
            p1 += l1 * at[j];
        }
        #pragma unroll
        for (int sh = 1; sh < 32; sh <<= 1) {
            if (sh < G) {
                p0 += __shfl_xor_sync(0xffffffffu, p0, sh);
                p1 += __shfl_xor_sync(0xffffffffu, p1, sh);
            }
        }
        float nm = fmaxf(m, fmaxf(p0, p1));
        float scale = __expf(m - nm);
        float w0 = __expf(p0 - nm);
        float w1 = __expf(p1 - nm);
        d = d * scale + w0 + w1;
        #pragma unroll
        for (int j = 0; j < 8; j++)
            acc[j] = acc[j] * scale + w0 * f0[j] + w1 * f1[j];
        m = nm;
    }
    if (p < s1) {
        int u = esrc[p];
        float fsu[8];
        load8h(ff + (size_t)u * FFS + lane * 8, fsu);
        float partial = 0.f;
        #pragma unroll
        for (int j = 0; j < 8; j++) {
            float e = fsu[j] + fdv[j];
            float el = (e > 0.f) ? e : SLOPE * e;
            partial += el * at[j];
        }
        #pragma unroll
        for (int sh = 1; sh < 32; sh <<= 1)
            if (sh < G) partial += __shfl_xor_sync(0xffffffffu, partial, sh);
        float nm = fmaxf(m, partial);
        float scale = __expf(m - nm);
        float w = __expf(partial - nm);
        d = d * scale + w;
        #pragma unroll
        for (int j = 0; j < 8; j++) acc[j] = acc[j] * scale + w * fsu[j];
        m = nm;
    }

    float inv = (s1 > s0) ? (1.f / d) : 0.f;
    if (OUT_HALF) {
        __half2 h[4];
        #pragma unroll
        for (int j = 0; j < 4; j++)
            h[j] = __floats2half2_rn(acc[2 * j] * inv, acc[2 * j + 1] * inv);
        *(uint4*)(outh + (size_t)v * FEAT + lane * 8) = *(uint4*)h;
    } else {
        float* op = outf + (size_t)v * FEAT + lane * 8;
        float4 o0, o1;
        o0.x = acc[0] * inv; o0.y = acc[1] * inv; o0.z = acc[2] * inv; o0.w = acc[3] * inv;
        o1.x = acc[4] * inv; o1.y = acc[5] * inv; o1.z = acc[6] * inv; o1.w = acc[7] * inv;
        *(float4*)(op) = o0;
        *(float4*)(op + 4) = o1;
    }
}

// ---------------- head ----------------
__global__ void build_combined(const float* __restrict__ h, const float* __restrict__ pooled,
                               const int* __restrict__ aidx, float* __restrict__ comb) {
    int i = blockIdx.x * blockDim.x + threadIdx.x;
    if (i >= BATCH * 1024) return;
    int b = i >> 10, j = i & 1023;
    if (j < 256) {
        float s = 0.f;
        #pragma unroll
        for (int a = 0; a < ASP; a++) {
            int node = aidx[b * ASP + a];
            s += h[(size_t)node * FEAT + j];
        }
        comb[i] = 0.25f * s;
    } else {
        comb[i] = pooled[(size_t)b * INDIM + (j - 256)];
    }
}

__global__ void __launch_bounds__(256)
head_mlp(const float* __restrict__ in, const float* __restrict__ W,
         const float* __restrict__ bias, float* __restrict__ out, int K, int relu) {
    __shared__ float row[1024];
    int b = blockIdx.x, j = threadIdx.x;
    for (int k = j; k < K; k += 256) row[k] = in[(size_t)b * K + k];
    __syncthreads();
    float sum = bias[j];
    for (int k = 0; k < K; k++) sum += row[k] * W[(size_t)k * 256 + j];
    if (relu) sum = fmaxf(sum, 0.f);
    out[(size_t)b * 256 + j] = sum;
}

// ---------------- launch ----------------
extern "C" void kernel_launch(void* const* d_in, const int* in_sizes, int n_in,
                              void* d_out, int out_size) {
    const float* x      = (const float*)d_in[0];
    const float* pooled = (const float*)d_in[1];
    const int*   src    = (const int*)d_in[2];
    const int*   dst    = (const int*)d_in[3];
    const int*   aidx   = (const int*)d_in[4];
    const float* Ws[3]  = {(const float*)d_in[5],  (const float*)d_in[10], (const float*)d_in[15]};
    const float* bs[3]  = {(const float*)d_in[6],  (const float*)d_in[11], (const float*)d_in[16]};
    const float* Wd[3]  = {(const float*)d_in[7],  (const float*)d_in[12], (const float*)d_in[17]};
    const float* bd[3]  = {(const float*)d_in[8],  (const float*)d_in[13], (const float*)d_in[18]};
    const float* attn[3]= {(const float*)d_in[9],  (const float*)d_in[14], (const float*)d_in[19]};
    const float* Wc1 = (const float*)d_in[20]; const float* bc1 = (const float*)d_in[21];
    const float* Wc2 = (const float*)d_in[22]; const float* bc2 = (const float*)d_in[23];
    const float* Wc3 = (const float*)d_in[24]; const float* bc3 = (const float*)d_in[25];
    float* out = (float*)d_out;

    __half *A, *B, *ff;
    float *h, *bias, *comb, *z1, *z2;
    int *deg, *off, *cur, *esrc;
    cudaGetSymbolAddress((void**)&A,    g_a);
    cudaGetSymbolAddress((void**)&B,    g_b);
    cudaGetSymbolAddress((void**)&ff,   g_ff);
    cudaGetSymbolAddress((void**)&h,    g_h);
    cudaGetSymbolAddress((void**)&bias, g_bias);
    cudaGetSymbolAddress((void**)&deg,  g_deg);
    cudaGetSymbolAddress((void**)&off,  g_off);
    cudaGetSymbolAddress((void**)&cur,  g_cur);
    cudaGetSymbolAddress((void**)&esrc, g_esrc);
    cudaGetSymbolAddress((void**)&comb, g_comb);
    cudaGetSymbolAddress((void**)&z1,   g_z1);
    cudaGetSymbolAddress((void**)&z2,   g_z2);

    cudaFuncSetAttribute(gemm_mma, cudaFuncAttributeMaxDynamicSharedMemorySize, SMEM_GEMM);

    dim3 ggrid(512 / BN, MPAD / BM);   // (4, 391)
    const int aggBlocks = (NN * 32 + 255) / 256;

    // ---- layer 0 prologue first, so the 5th GPU op is gemm_mma(K=768) for ncu ----
    conv_a_f16<<<(MPAD * (INDIM / 4) + 255) / 256, 256>>>(x, A, NN, INDIM);       // 1
    conv_b_f16<<<(512 * INDIM + 255) / 256, 256>>>(Ws[0], Wd[0], B, INDIM);       // 2
    concat_bias<<<1, 512>>>(bs[0], bd[0], bias);                                  // 3
    cudaMemsetAsync(deg, 0, NN * sizeof(int));                                    // 4
    gemm_mma<<<ggrid, 256, SMEM_GEMM>>>(A, B, bias, ff, INDIM);                   // 5 <- profiled

    // ---- CSR build (independent of gemm; must finish before edge_agg) ----
    hist_kernel<<<(NE + 255) / 256, 256>>>(dst, deg);
    scan_kernel<<<1, 1024>>>(deg, off, cur);
    scatter_kernel<<<(NE + 255) / 256, 256>>>(src, dst, cur, esrc);

    // ---- layer 0 edge stage ----
    edge_agg<true><<<aggBlocks, 256>>>(ff, attn[0], off, esrc, A, nullptr, 8);
    cudaMemsetAsync(A + (size_t)NN * FEAT, 0, (size_t)(MPAD - NN) * FEAT * sizeof(__half));

    // ---- layer 1: input A fp16 [MPAD, 256] ----
    {
        int K = FEAT;
        conv_b_f16<<<(512 * K + 255) / 256, 256>>>(Ws[1], Wd[1], B, K);
        concat_bias<<<1, 512>>>(bs[1], bd[1], bias);
        gemm_mma<<<ggrid, 256, SMEM_GEMM>>>(A, B, bias, ff, K);
        edge_agg<true><<<aggBlocks, 256>>>(ff, attn[1], off, esrc, A, nullptr, 8);
    }
    // ---- layer 2: heads=1 fout=256 -> G=32, fp32 output for head ----
    {
        int K = FEAT;
        conv_b_f16<<<(512 * K + 255) / 256, 256>>>(Ws[2], Wd[2], B, K);
        concat_bias<<<1, 512>>>(bs[2], bd[2], bias);
        gemm_mma<<<ggrid, 256, SMEM_GEMM>>>(A, B, bias, ff, K);
        edge_agg<false><<<aggBlocks, 256>>>(ff, attn[2], off, esrc, nullptr, h, 32);
    }

    // ---- head ----
    build_combined<<<(BATCH * 1024 + 255) / 256, 256>>>(h, pooled, aidx, comb);
    head_mlp<<<BATCH, 256>>>(comb, Wc1, bc1, z1, 1024, 0);
    head_mlp<<<BATCH, 256>>>(z1,   Wc2, bc2, z2, 256, 1);
    head_mlp<<<BATCH, 256>>>(z2,   Wc3, bc3, out, 256, 0);
}